// round 1
// baseline (speedup 1.0000x reference)
#include <cuda_runtime.h>
#include <stdint.h>

#define Bb 4
#define Tt 512
#define DIN 2048
#define Hh 16
#define Gg 4
#define HD 128
#define CACHEN 3584
#define SS 4096

// Scratch (static device arrays; no allocation allowed)
__device__ float g_q_raw[Bb*Tt*Hh*HD];   // [B*T, H*HD]
__device__ float g_k_raw[Bb*Tt*Gg*HD];   // [B*T, G*HD]
__device__ float g_v_raw[Bb*Tt*Gg*HD];   // [B*T, G*HD]
__device__ float g_q    [Bb*Hh*Tt*HD];   // [B,H,T,HD]
__device__ float g_ctx  [Bb*Tt*Hh*HD];   // [B,T,H,HD]

// ---------------------------------------------------------------------------
// Tiled fp32 GEMM: C[M,N] = A[M,K] @ B[K,N].  BM=BN=64, BK=16, 256 threads,
// 4x4 register tile per thread. Dims here are always multiples of 64/16.
// ---------------------------------------------------------------------------
__global__ __launch_bounds__(256) void gemm_kernel(
    const float* __restrict__ A, const float* __restrict__ Bm,
    float* __restrict__ C, int M, int N, int K)
{
    __shared__ float As[16][64];
    __shared__ float Bs[16][64];
    int tid = threadIdx.x;
    int tx = tid & 15, ty = tid >> 4;
    int m0 = blockIdx.y << 6, n0 = blockIdx.x << 6;
    float acc[4][4] = {{0.f}};
    for (int k0 = 0; k0 < K; k0 += 16) {
        #pragma unroll
        for (int i = 0; i < 4; i++) {
            int idx = tid + i * 256;
            int m = idx >> 4, k = idx & 15;
            As[k][m] = A[(size_t)(m0 + m) * K + k0 + k];
            int kb = idx >> 6, n = idx & 63;
            Bs[kb][n] = Bm[(size_t)(k0 + kb) * N + n0 + n];
        }
        __syncthreads();
        #pragma unroll
        for (int kk = 0; kk < 16; kk++) {
            float a[4], b[4];
            #pragma unroll
            for (int i = 0; i < 4; i++) a[i] = As[kk][ty * 4 + i];
            #pragma unroll
            for (int j = 0; j < 4; j++) b[j] = Bs[kk][tx * 4 + j];
            #pragma unroll
            for (int i = 0; i < 4; i++)
                #pragma unroll
                for (int j = 0; j < 4; j++)
                    acc[i][j] = fmaf(a[i], b[j], acc[i][j]);
        }
        __syncthreads();
    }
    #pragma unroll
    for (int i = 0; i < 4; i++)
        #pragma unroll
        for (int j = 0; j < 4; j++)
            C[(size_t)(m0 + ty * 4 + i) * N + n0 + tx * 4 + j] = acc[i][j];
}

// ---------------------------------------------------------------------------
// Fused per-head RMSNorm + RoPE. One 128-thread block per (b,t,head) row.
// raw layout: [(b*T+t)*NH + h][HD].  out layout: [b, NH, Tout, HD] at t+toff.
// ---------------------------------------------------------------------------
__global__ __launch_bounds__(128) void norm_rope_kernel(
    const float* __restrict__ raw, const float* __restrict__ nw,
    const float* __restrict__ cosT, const float* __restrict__ sinT,
    const int* __restrict__ pos, float* __restrict__ out,
    int NH, int Tout, int toff)
{
    int idx = blockIdx.x;          // (b*T + t)*NH + h
    int h  = idx % NH;
    int bt = idx / NH;
    int t  = bt % Tt;
    int b  = bt / Tt;
    int d  = threadIdx.x;

    __shared__ float zn[128];
    __shared__ float red[4];

    float z = raw[(size_t)idx * HD + d];
    float ss = z * z;
    #pragma unroll
    for (int o = 16; o; o >>= 1) ss += __shfl_xor_sync(0xffffffffu, ss, o);
    if ((d & 31) == 0) red[d >> 5] = ss;
    __syncthreads();
    float tot = red[0] + red[1] + red[2] + red[3];
    float r = rsqrtf(tot * (1.0f / 128.0f) + 1e-6f);
    float v = z * r * nw[d];
    zn[d] = v;
    __syncthreads();

    int p = pos[bt];
    float c = cosT[p * HD + d];
    float s = sinT[p * HD + d];
    float rot = (d < 64) ? -zn[d + 64] : zn[d - 64];
    float o = fmaf(v, c, rot * s);
    out[(((size_t)b * NH + h) * Tout + (toff + t)) * HD + d] = o;
}

// ---------------------------------------------------------------------------
// V scatter: v_full[b,g,CACHE+t,d] = v_raw[(b*T+t)*G + g][d]
// ---------------------------------------------------------------------------
__global__ __launch_bounds__(256) void scatter_v_kernel(
    const float* __restrict__ vr, float* __restrict__ vf)
{
    int i = blockIdx.x * blockDim.x + threadIdx.x;
    const int n = Bb * Tt * Gg * HD;
    if (i >= n) return;
    int d = i & 127;
    int g = (i >> 7) & 3;
    int t = (i >> 9) % Tt;
    int b = i / (HD * Gg * Tt);
    vf[(((size_t)(b * Gg + g)) * SS + CACHEN + t) * HD + d] = vr[i];
}

// ---------------------------------------------------------------------------
// Cache copy: dst[b,g,0:CACHE,:] = src[b,g,:,:]  (float4)
// ---------------------------------------------------------------------------
__global__ __launch_bounds__(256) void copy_cache_kernel(
    const float4* __restrict__ src, float4* __restrict__ dst)
{
    int i = blockIdx.x * blockDim.x + threadIdx.x;
    const int per = CACHEN * HD / 4;           // per (b,g)
    const int n4  = Bb * Gg * per;
    if (i >= n4) return;
    int bg = i / per, r = i % per;
    dst[(size_t)bg * (SS * HD / 4) + r] = src[i];
}

// ---------------------------------------------------------------------------
// Flash attention, fp32, online softmax.
// grid = (T/64, H, B), 256 threads. Tiles: 64 queries x 64 keys, HD=128.
// smem: Qt[128][65], Kt[128][65], Vs[64][128], Pt[64][65], m/l/alpha[64]
// ---------------------------------------------------------------------------
__global__ __launch_bounds__(256) void attn_kernel(
    const float* __restrict__ q, const float* __restrict__ kf,
    const float* __restrict__ vf, const uint8_t* __restrict__ mask,
    float* __restrict__ ctx)
{
    extern __shared__ float sm[];
    float* Qt  = sm;                   // [128][65]
    float* Kt  = Qt + 128 * 65;        // [128][65]
    float* Vs  = Kt + 128 * 65;        // [64][128]
    float* Pt  = Vs + 64 * 128;        // [64][65]
    float* m_s = Pt + 64 * 65;         // [64]
    float* l_s = m_s + 64;             // [64]
    float* al_s = l_s + 64;            // [64]

    int qt = blockIdx.x, h = blockIdx.y, b = blockIdx.z;
    int g = h >> 2;                    // H/G = 4
    int tid = threadIdx.x;
    int tx = tid & 15, ty = tid >> 4;
    const float scale = 0.08838834764831845f;  // 1/sqrt(128)

    const float* qbase = q + (((size_t)b * Hh + h) * Tt + qt * 64) * HD;
    for (int i = tid; i < 64 * 128; i += 256) {
        int qi = i >> 7, d = i & 127;
        Qt[d * 65 + qi] = qbase[i] * scale;
    }
    if (tid < 64) { m_s[tid] = -1e30f; l_s[tid] = 0.0f; }

    float oacc[4][8];
    #pragma unroll
    for (int i = 0; i < 4; i++)
        #pragma unroll
        for (int j = 0; j < 8; j++) oacc[i][j] = 0.0f;
    __syncthreads();

    const float* kbase = kf + (size_t)(b * Gg + g) * SS * HD;
    const float* vbase = vf + (size_t)(b * Gg + g) * SS * HD;
    const uint8_t* mbase = mask + ((size_t)b * Tt + qt * 64) * SS;

    for (int s0 = 0; s0 < SS; s0 += 64) {
        // load K,V tiles
        for (int i = tid; i < 64 * 128; i += 256) {
            int si = i >> 7, d = i & 127;
            Kt[d * 65 + si] = kbase[(size_t)s0 * HD + i];
            Vs[i]           = vbase[(size_t)s0 * HD + i];
        }
        __syncthreads();

        // scores: thread owns rows qi=ty*4.., cols si=tx*4..
        float sc[4][4];
        #pragma unroll
        for (int i = 0; i < 4; i++)
            #pragma unroll
            for (int j = 0; j < 4; j++) sc[i][j] = 0.0f;

        #pragma unroll 4
        for (int kk = 0; kk < 128; kk++) {
            float a[4], bv[4];
            #pragma unroll
            for (int i = 0; i < 4; i++) a[i]  = Qt[kk * 65 + ty * 4 + i];
            #pragma unroll
            for (int j = 0; j < 4; j++) bv[j] = Kt[kk * 65 + tx * 4 + j];
            #pragma unroll
            for (int i = 0; i < 4; i++)
                #pragma unroll
                for (int j = 0; j < 4; j++)
                    sc[i][j] = fmaf(a[i], bv[j], sc[i][j]);
        }

        // mask (True = masked out)
        #pragma unroll
        for (int i = 0; i < 4; i++) {
            int qi = ty * 4 + i;
            #pragma unroll
            for (int j = 0; j < 4; j++)
                if (mbase[(size_t)qi * SS + s0 + tx * 4 + j]) sc[i][j] = -1e30f;
        }

        // row max across the 16-lane tx group
        float rmax[4];
        #pragma unroll
        for (int i = 0; i < 4; i++) {
            float mx = fmaxf(fmaxf(sc[i][0], sc[i][1]), fmaxf(sc[i][2], sc[i][3]));
            #pragma unroll
            for (int o = 8; o; o >>= 1)
                mx = fmaxf(mx, __shfl_xor_sync(0xffffffffu, mx, o));
            rmax[i] = mx;
        }
        if (tx == 0) {
            #pragma unroll
            for (int i = 0; i < 4; i++) {
                int row = ty * 4 + i;
                float mo = m_s[row];
                float mn = fmaxf(mo, rmax[i]);
                m_s[row] = mn;
                al_s[row] = __expf(mo - mn);
            }
        }
        __syncthreads();

        // P = exp(sc - m_new), transpose into Pt[si][qi], row sums
        float rsum[4];
        #pragma unroll
        for (int i = 0; i < 4; i++) {
            int row = ty * 4 + i;
            float mn = m_s[row];
            float rs = 0.0f;
            #pragma unroll
            for (int j = 0; j < 4; j++) {
                float p = __expf(sc[i][j] - mn);
                Pt[(tx * 4 + j) * 65 + row] = p;
                rs += p;
            }
            #pragma unroll
            for (int o = 8; o; o >>= 1)
                rs += __shfl_xor_sync(0xffffffffu, rs, o);
            rsum[i] = rs;
        }
        if (tx == 0) {
            #pragma unroll
            for (int i = 0; i < 4; i++) {
                int row = ty * 4 + i;
                l_s[row] = l_s[row] * al_s[row] + rsum[i];
            }
        }
        __syncthreads();

        // PV: thread owns rows qi=ty*4.., cols d=tx*8..
        float alpha[4];
        #pragma unroll
        for (int i = 0; i < 4; i++) alpha[i] = al_s[ty * 4 + i];
        #pragma unroll
        for (int i = 0; i < 4; i++)
            #pragma unroll
            for (int j = 0; j < 8; j++) oacc[i][j] *= alpha[i];

        #pragma unroll 2
        for (int si = 0; si < 64; si++) {
            float p[4];
            #pragma unroll
            for (int i = 0; i < 4; i++) p[i] = Pt[si * 65 + ty * 4 + i];
            float4 v0 = *(const float4*)&Vs[si * 128 + tx * 8];
            float4 v1 = *(const float4*)&Vs[si * 128 + tx * 8 + 4];
            #pragma unroll
            for (int i = 0; i < 4; i++) {
                oacc[i][0] = fmaf(p[i], v0.x, oacc[i][0]);
                oacc[i][1] = fmaf(p[i], v0.y, oacc[i][1]);
                oacc[i][2] = fmaf(p[i], v0.z, oacc[i][2]);
                oacc[i][3] = fmaf(p[i], v0.w, oacc[i][3]);
                oacc[i][4] = fmaf(p[i], v1.x, oacc[i][4]);
                oacc[i][5] = fmaf(p[i], v1.y, oacc[i][5]);
                oacc[i][6] = fmaf(p[i], v1.z, oacc[i][6]);
                oacc[i][7] = fmaf(p[i], v1.w, oacc[i][7]);
            }
        }
        __syncthreads();
    }

    // epilogue: ctx[b, t, h, d] = O / l
    #pragma unroll
    for (int i = 0; i < 4; i++) {
        int qi = ty * 4 + i;
        float il = 1.0f / l_s[qi];
        int t = qt * 64 + qi;
        float* dst = ctx + (((size_t)b * Tt + t) * Hh + h) * HD + tx * 8;
        #pragma unroll
        for (int j = 0; j < 8; j++) dst[j] = oacc[i][j] * il;
    }
}

// ---------------------------------------------------------------------------
extern "C" void kernel_launch(void* const* d_in, const int* in_sizes, int n_in,
                              void* d_out, int out_size)
{
    const float*   x       = (const float*)d_in[0];
    const uint8_t* mask    = (const uint8_t*)d_in[1];
    const float*   cosT    = (const float*)d_in[2];
    const float*   sinT    = (const float*)d_in[3];
    const int*     pos     = (const int*)d_in[4];
    const float*   cache_k = (const float*)d_in[5];
    const float*   cache_v = (const float*)d_in[6];
    const float*   q_w     = (const float*)d_in[7];
    const float*   k_w     = (const float*)d_in[8];
    const float*   v_w     = (const float*)d_in[9];
    const float*   o_w     = (const float*)d_in[10];
    const float*   qn_w    = (const float*)d_in[11];
    const float*   kn_w    = (const float*)d_in[12];

    float* out_ctx = (float*)d_out;                                 // [B,T,H*HD]
    float* out_k   = out_ctx + (size_t)Bb * Tt * Hh * HD;           // [B,G,S,HD]
    float* out_v   = out_k   + (size_t)Bb * Gg * SS * HD;           // [B,G,S,HD]

    float *q_raw, *k_raw, *v_raw, *qf, *ctx;
    cudaGetSymbolAddress((void**)&q_raw, g_q_raw);
    cudaGetSymbolAddress((void**)&k_raw, g_k_raw);
    cudaGetSymbolAddress((void**)&v_raw, g_v_raw);
    cudaGetSymbolAddress((void**)&qf,    g_q);
    cudaGetSymbolAddress((void**)&ctx,   g_ctx);

    // cache halves of k_full / v_full
    {
        int n4 = Bb * Gg * CACHEN * HD / 4;
        int blocks = (n4 + 255) / 256;
        copy_cache_kernel<<<blocks, 256>>>((const float4*)cache_k, (float4*)out_k);
        copy_cache_kernel<<<blocks, 256>>>((const float4*)cache_v, (float4*)out_v);
    }

    // projections
    gemm_kernel<<<dim3(32, 32), 256>>>(x, q_w, q_raw, 2048, 2048, 2048);
    gemm_kernel<<<dim3(8, 32),  256>>>(x, k_w, k_raw, 2048, 512,  2048);
    gemm_kernel<<<dim3(8, 32),  256>>>(x, v_w, v_raw, 2048, 512,  2048);

    // RMSNorm + RoPE; K goes straight into k_full's new-token region
    norm_rope_kernel<<<Bb * Tt * Hh, 128>>>(q_raw, qn_w, cosT, sinT, pos, qf,    Hh, Tt, 0);
    norm_rope_kernel<<<Bb * Tt * Gg, 128>>>(k_raw, kn_w, cosT, sinT, pos, out_k, Gg, SS, CACHEN);

    // V into v_full's new-token region
    {
        int n = Bb * Tt * Gg * HD;
        scatter_v_kernel<<<(n + 255) / 256, 256>>>(v_raw, out_v);
    }

    // attention
    size_t smem = (size_t)(128 * 65 * 2 + 64 * 128 + 64 * 65 + 3 * 64) * sizeof(float);
    cudaFuncSetAttribute(attn_kernel, cudaFuncAttributeMaxDynamicSharedMemorySize, (int)smem);
    attn_kernel<<<dim3(Tt / 64, Hh, Bb), 256, smem>>>(qf, out_k, out_v, mask, ctx);

    // output projection
    gemm_kernel<<<dim3(32, 32), 256>>>(ctx, o_w, out_ctx, 2048, 2048, 2048);
}

// round 2
// speedup vs baseline: 4.0065x; 4.0065x over previous
#include <cuda_runtime.h>
#include <stdint.h>

#define Bb 4
#define Tt 512
#define Hh 16
#define Gg 4
#define HD 128
#define CACHEN 3584
#define SS 4096

// Scratch (static device arrays; no allocation allowed)
__device__ float g_q_raw[Bb*Tt*Hh*HD];   // [B*T, H*HD]
__device__ float g_k_raw[Bb*Tt*Gg*HD];   // [B*T, G*HD]
__device__ float g_v_raw[Bb*Tt*Gg*HD];   // [B*T, G*HD]
__device__ float g_q    [Bb*Hh*Tt*HD];   // [B,H,T,HD]
__device__ float g_ctx  [Bb*Tt*Hh*HD];   // [B,T,H,HD]

__device__ __forceinline__ unsigned f2t(float x) {
    unsigned r;
    asm("cvt.rna.tf32.f32 %0, %1;" : "=r"(r) : "f"(x));
    return r;
}

__device__ __forceinline__ void mma8(float* c,
    unsigned a0, unsigned a1, unsigned a2, unsigned a3,
    unsigned b0, unsigned b1)
{
    asm volatile(
        "mma.sync.aligned.m16n8k8.row.col.f32.tf32.tf32.f32 "
        "{%0,%1,%2,%3}, {%4,%5,%6,%7}, {%8,%9}, {%0,%1,%2,%3};"
        : "+f"(c[0]), "+f"(c[1]), "+f"(c[2]), "+f"(c[3])
        : "r"(a0), "r"(a1), "r"(a2), "r"(a3), "r"(b0), "r"(b1));
}

// ---------------------------------------------------------------------------
// tf32 tensor-core GEMM: C[M,N] = A[M,K] @ B[K,N], row-major fp32 in/out.
// Block tile 128x128, BK=16, 256 threads = 8 warps (2x4), warp tile 64x32.
// ---------------------------------------------------------------------------
__global__ __launch_bounds__(256) void gemm_tf32(
    const float* __restrict__ A, const float* __restrict__ Bm,
    float* __restrict__ C, int M, int N, int K)
{
    __shared__ unsigned As[128 * 20];   // [m][k], stride 20 (conflict-free frags)
    __shared__ unsigned Bs[16 * 136];   // [k][n], stride 136

    int tid = threadIdx.x, lane = tid & 31, warp = tid >> 5;
    int g = lane >> 2, tg = lane & 3;
    int m0 = blockIdx.y << 7, n0 = blockIdx.x << 7;
    int wm = (warp >> 2) << 6, wn = (warp & 3) << 5;

    float acc[4][4][4];
    #pragma unroll
    for (int i = 0; i < 4; i++)
        #pragma unroll
        for (int j = 0; j < 4; j++)
            #pragma unroll
            for (int e = 0; e < 4; e++) acc[i][j][e] = 0.0f;

    for (int k0 = 0; k0 < K; k0 += 16) {
        #pragma unroll
        for (int i = tid; i < 512; i += 256) {
            int r = i >> 2, cg = (i & 3) << 2;
            float4 v = *(const float4*)&A[(size_t)(m0 + r) * K + k0 + cg];
            uint4 u;
            u.x = f2t(v.x); u.y = f2t(v.y); u.z = f2t(v.z); u.w = f2t(v.w);
            *(uint4*)&As[r * 20 + cg] = u;

            int rb = i >> 5, cb = (i & 31) << 2;
            float4 w = *(const float4*)&Bm[(size_t)(k0 + rb) * N + n0 + cb];
            uint4 u2;
            u2.x = f2t(w.x); u2.y = f2t(w.y); u2.z = f2t(w.z); u2.w = f2t(w.w);
            *(uint4*)&Bs[rb * 136 + cb] = u2;
        }
        __syncthreads();

        #pragma unroll
        for (int ks = 0; ks < 16; ks += 8) {
            unsigned a[4][4];
            #pragma unroll
            for (int mt = 0; mt < 4; mt++) {
                int r = wm + mt * 16;
                a[mt][0] = As[(r + g) * 20 + ks + tg];
                a[mt][1] = As[(r + g + 8) * 20 + ks + tg];
                a[mt][2] = As[(r + g) * 20 + ks + tg + 4];
                a[mt][3] = As[(r + g + 8) * 20 + ks + tg + 4];
            }
            #pragma unroll
            for (int nt = 0; nt < 4; nt++) {
                unsigned b0 = Bs[(ks + tg) * 136 + wn + nt * 8 + g];
                unsigned b1 = Bs[(ks + tg + 4) * 136 + wn + nt * 8 + g];
                #pragma unroll
                for (int mt = 0; mt < 4; mt++)
                    mma8(acc[mt][nt], a[mt][0], a[mt][1], a[mt][2], a[mt][3], b0, b1);
            }
        }
        __syncthreads();
    }

    #pragma unroll
    for (int mt = 0; mt < 4; mt++)
        #pragma unroll
        for (int nt = 0; nt < 4; nt++) {
            int r0 = m0 + wm + mt * 16 + g;
            int c  = n0 + wn + nt * 8 + 2 * tg;
            float2 v0 = make_float2(acc[mt][nt][0], acc[mt][nt][1]);
            float2 v1 = make_float2(acc[mt][nt][2], acc[mt][nt][3]);
            *(float2*)&C[(size_t)r0 * N + c] = v0;
            *(float2*)&C[(size_t)(r0 + 8) * N + c] = v1;
        }
}

// ---------------------------------------------------------------------------
// Fused per-head RMSNorm + RoPE (unchanged from round 1).
// ---------------------------------------------------------------------------
__global__ __launch_bounds__(128) void norm_rope_kernel(
    const float* __restrict__ raw, const float* __restrict__ nw,
    const float* __restrict__ cosT, const float* __restrict__ sinT,
    const int* __restrict__ pos, float* __restrict__ out,
    int NH, int Tout, int toff)
{
    int idx = blockIdx.x;          // (b*T + t)*NH + h
    int h  = idx % NH;
    int bt = idx / NH;
    int t  = bt % Tt;
    int b  = bt / Tt;
    int d  = threadIdx.x;

    __shared__ float zn[128];
    __shared__ float red[4];

    float z = raw[(size_t)idx * HD + d];
    float ss = z * z;
    #pragma unroll
    for (int o = 16; o; o >>= 1) ss += __shfl_xor_sync(0xffffffffu, ss, o);
    if ((d & 31) == 0) red[d >> 5] = ss;
    __syncthreads();
    float tot = red[0] + red[1] + red[2] + red[3];
    float r = rsqrtf(tot * (1.0f / 128.0f) + 1e-6f);
    float v = z * r * nw[d];
    zn[d] = v;
    __syncthreads();

    int p = pos[bt];
    float c = cosT[p * HD + d];
    float s = sinT[p * HD + d];
    float rot = (d < 64) ? -zn[d + 64] : zn[d - 64];
    float o = fmaf(v, c, rot * s);
    out[(((size_t)b * NH + h) * Tout + (toff + t)) * HD + d] = o;
}

__global__ __launch_bounds__(256) void scatter_v_kernel(
    const float* __restrict__ vr, float* __restrict__ vf)
{
    int i = blockIdx.x * blockDim.x + threadIdx.x;
    const int n = Bb * Tt * Gg * HD;
    if (i >= n) return;
    int d = i & 127;
    int g = (i >> 7) & 3;
    int t = (i >> 9) % Tt;
    int b = i / (HD * Gg * Tt);
    vf[(((size_t)(b * Gg + g)) * SS + CACHEN + t) * HD + d] = vr[i];
}

__global__ __launch_bounds__(256) void copy_cache_kernel(
    const float4* __restrict__ src, float4* __restrict__ dst)
{
    int i = blockIdx.x * blockDim.x + threadIdx.x;
    const int per = CACHEN * HD / 4;
    const int n4  = Bb * Gg * per;
    if (i >= n4) return;
    int bg = i / per, r = i % per;
    dst[(size_t)bg * (SS * HD / 4) + r] = src[i];
}

// ---------------------------------------------------------------------------
// tf32 flash attention. grid=(T/128, H, B), 256 threads = 8 warps.
// Each warp owns 16 query rows; online softmax in registers (lane-quad rows).
// Key tiles of 64; P->A fragment built via intra-quad shfls (no smem trip).
// ---------------------------------------------------------------------------
__global__ __launch_bounds__(256) void attn_tf32(
    const float* __restrict__ q, const float* __restrict__ kf,
    const float* __restrict__ vf, const uint8_t* __restrict__ mask,
    float* __restrict__ ctx)
{
    extern __shared__ char smraw[];
    unsigned* Qs = (unsigned*)smraw;         // [128][132] tf32 bits
    unsigned* Ks = Qs + 128 * 132;           // [64][132]
    unsigned* Vs = Ks + 64 * 132;            // [64][136]
    uint8_t*  Msk = (uint8_t*)(Vs + 64 * 136); // [128][64]

    int qt = blockIdx.x, h = blockIdx.y, b = blockIdx.z;
    int gh = h >> 2;                          // KV head (H/G = 4)
    int tid = threadIdx.x, lane = tid & 31, wq = tid >> 5;
    int g = lane >> 2, tg = lane & 3;
    const float scale = 0.08838834764831845f;  // 1/sqrt(128)

    // Load + scale + tf32-convert Q tile [128][128]
    const float* qb = q + (((size_t)b * Hh + h) * Tt + qt * 128) * HD;
    for (int i = tid; i < 4096; i += 256) {
        int r = i >> 5, cg = (i & 31) << 2;
        float4 v = *(const float4*)&qb[(size_t)r * HD + cg];
        uint4 u;
        u.x = f2t(v.x * scale); u.y = f2t(v.y * scale);
        u.z = f2t(v.z * scale); u.w = f2t(v.w * scale);
        *(uint4*)&Qs[r * 132 + cg] = u;
    }

    float oacc[16][4];
    #pragma unroll
    for (int nt = 0; nt < 16; nt++)
        #pragma unroll
        for (int e = 0; e < 4; e++) oacc[nt][e] = 0.0f;
    float m0r = -1e30f, m1r = -1e30f, l0 = 0.0f, l1 = 0.0f;

    const float* kb = kf + ((size_t)b * Gg + gh) * SS * HD;
    const float* vb = vf + ((size_t)b * Gg + gh) * SS * HD;
    const uint8_t* mb = mask + ((size_t)b * Tt + qt * 128) * SS;
    int qrow = wq * 16;

    for (int s0 = 0; s0 < SS; s0 += 64) {
        // stage K, V (tf32) and mask tile
        for (int i = tid; i < 2048; i += 256) {
            int r = i >> 5, cg = (i & 31) << 2;
            float4 kv = *(const float4*)&kb[(size_t)(s0 + r) * HD + cg];
            uint4 uk;
            uk.x = f2t(kv.x); uk.y = f2t(kv.y); uk.z = f2t(kv.z); uk.w = f2t(kv.w);
            *(uint4*)&Ks[r * 132 + cg] = uk;
            float4 vv = *(const float4*)&vb[(size_t)(s0 + r) * HD + cg];
            uint4 uv;
            uv.x = f2t(vv.x); uv.y = f2t(vv.y); uv.z = f2t(vv.z); uv.w = f2t(vv.w);
            *(uint4*)&Vs[r * 136 + cg] = uv;
        }
        for (int i = tid; i < 512; i += 256) {
            int r = i >> 2, c = (i & 3) << 4;
            *(uint4*)&Msk[r * 64 + c] = *(const uint4*)&mb[(size_t)r * SS + s0 + c];
        }
        __syncthreads();

        // S = Q K^T for this warp's 16 rows x 64 keys
        float sacc[8][4];
        #pragma unroll
        for (int nt = 0; nt < 8; nt++)
            #pragma unroll
            for (int e = 0; e < 4; e++) sacc[nt][e] = 0.0f;

        #pragma unroll
        for (int ks = 0; ks < 128; ks += 8) {
            unsigned a0 = Qs[(qrow + g) * 132 + ks + tg];
            unsigned a1 = Qs[(qrow + g + 8) * 132 + ks + tg];
            unsigned a2 = Qs[(qrow + g) * 132 + ks + tg + 4];
            unsigned a3 = Qs[(qrow + g + 8) * 132 + ks + tg + 4];
            #pragma unroll
            for (int nt = 0; nt < 8; nt++) {
                unsigned b0 = Ks[(nt * 8 + g) * 132 + ks + tg];
                unsigned b1 = Ks[(nt * 8 + g) * 132 + ks + tg + 4];
                mma8(sacc[nt], a0, a1, a2, a3, b0, b1);
            }
        }

        // mask (True = masked out)
        #pragma unroll
        for (int nt = 0; nt < 8; nt++) {
            unsigned short mm0 = *(const unsigned short*)&Msk[(qrow + g) * 64 + nt * 8 + 2 * tg];
            unsigned short mm1 = *(const unsigned short*)&Msk[(qrow + g + 8) * 64 + nt * 8 + 2 * tg];
            if (mm0 & 0x00FF) sacc[nt][0] = -1e30f;
            if (mm0 & 0xFF00) sacc[nt][1] = -1e30f;
            if (mm1 & 0x00FF) sacc[nt][2] = -1e30f;
            if (mm1 & 0xFF00) sacc[nt][3] = -1e30f;
        }

        // online softmax: rows live in a lane quad
        float mx0 = -1e30f, mx1 = -1e30f;
        #pragma unroll
        for (int nt = 0; nt < 8; nt++) {
            mx0 = fmaxf(mx0, fmaxf(sacc[nt][0], sacc[nt][1]));
            mx1 = fmaxf(mx1, fmaxf(sacc[nt][2], sacc[nt][3]));
        }
        mx0 = fmaxf(mx0, __shfl_xor_sync(0xffffffffu, mx0, 1));
        mx0 = fmaxf(mx0, __shfl_xor_sync(0xffffffffu, mx0, 2));
        mx1 = fmaxf(mx1, __shfl_xor_sync(0xffffffffu, mx1, 1));
        mx1 = fmaxf(mx1, __shfl_xor_sync(0xffffffffu, mx1, 2));
        float mn0 = fmaxf(m0r, mx0), mn1 = fmaxf(m1r, mx1);
        float al0 = __expf(m0r - mn0), al1 = __expf(m1r - mn1);
        m0r = mn0; m1r = mn1;

        unsigned pu[8][4];
        float rs0 = 0.0f, rs1 = 0.0f;
        #pragma unroll
        for (int nt = 0; nt < 8; nt++) {
            float p0 = __expf(sacc[nt][0] - mn0);
            float p1 = __expf(sacc[nt][1] - mn0);
            float p2 = __expf(sacc[nt][2] - mn1);
            float p3 = __expf(sacc[nt][3] - mn1);
            rs0 += p0 + p1; rs1 += p2 + p3;
            pu[nt][0] = f2t(p0); pu[nt][1] = f2t(p1);
            pu[nt][2] = f2t(p2); pu[nt][3] = f2t(p3);
        }
        rs0 += __shfl_xor_sync(0xffffffffu, rs0, 1);
        rs0 += __shfl_xor_sync(0xffffffffu, rs0, 2);
        rs1 += __shfl_xor_sync(0xffffffffu, rs1, 1);
        rs1 += __shfl_xor_sync(0xffffffffu, rs1, 2);
        l0 = l0 * al0 + rs0;
        l1 = l1 * al1 + rs1;

        #pragma unroll
        for (int nt = 0; nt < 16; nt++) {
            oacc[nt][0] *= al0; oacc[nt][1] *= al0;
            oacc[nt][2] *= al1; oacc[nt][3] *= al1;
        }

        // PV: A-fragments of P built via intra-quad shfls
        int base = lane & ~3, hs = tg >> 1, sel = tg & 1;
        #pragma unroll
        for (int kt = 0; kt < 8; kt++) {
            unsigned q0 = __shfl_sync(0xffffffffu, pu[kt][0], base + hs);
            unsigned q1 = __shfl_sync(0xffffffffu, pu[kt][1], base + hs);
            unsigned a0 = sel ? q1 : q0;
            unsigned q2 = __shfl_sync(0xffffffffu, pu[kt][0], base + hs + 2);
            unsigned q3 = __shfl_sync(0xffffffffu, pu[kt][1], base + hs + 2);
            unsigned a2 = sel ? q3 : q2;
            unsigned r0 = __shfl_sync(0xffffffffu, pu[kt][2], base + hs);
            unsigned r1 = __shfl_sync(0xffffffffu, pu[kt][3], base + hs);
            unsigned a1 = sel ? r1 : r0;
            unsigned r2 = __shfl_sync(0xffffffffu, pu[kt][2], base + hs + 2);
            unsigned r3 = __shfl_sync(0xffffffffu, pu[kt][3], base + hs + 2);
            unsigned a3 = sel ? r3 : r2;
            #pragma unroll
            for (int nt = 0; nt < 16; nt++) {
                unsigned b0 = Vs[(kt * 8 + tg) * 136 + nt * 8 + g];
                unsigned b1 = Vs[(kt * 8 + tg + 4) * 136 + nt * 8 + g];
                mma8(oacc[nt], a0, a1, a2, a3, b0, b1);
            }
        }
        __syncthreads();
    }

    // epilogue: ctx[b, t, h, d] = O / l
    float il0 = 1.0f / l0, il1 = 1.0f / l1;
    int tok0 = qt * 128 + qrow + g;
    #pragma unroll
    for (int nt = 0; nt < 16; nt++) {
        int d = nt * 8 + 2 * tg;
        float2 v0 = make_float2(oacc[nt][0] * il0, oacc[nt][1] * il0);
        float2 v1 = make_float2(oacc[nt][2] * il1, oacc[nt][3] * il1);
        *(float2*)&ctx[(((size_t)b * Tt + tok0) * Hh + h) * HD + d] = v0;
        *(float2*)&ctx[(((size_t)b * Tt + tok0 + 8) * Hh + h) * HD + d] = v1;
    }
}

// ---------------------------------------------------------------------------
extern "C" void kernel_launch(void* const* d_in, const int* in_sizes, int n_in,
                              void* d_out, int out_size)
{
    const float*   x       = (const float*)d_in[0];
    const uint8_t* mask    = (const uint8_t*)d_in[1];
    const float*   cosT    = (const float*)d_in[2];
    const float*   sinT    = (const float*)d_in[3];
    const int*     pos     = (const int*)d_in[4];
    const float*   cache_k = (const float*)d_in[5];
    const float*   cache_v = (const float*)d_in[6];
    const float*   q_w     = (const float*)d_in[7];
    const float*   k_w     = (const float*)d_in[8];
    const float*   v_w     = (const float*)d_in[9];
    const float*   o_w     = (const float*)d_in[10];
    const float*   qn_w    = (const float*)d_in[11];
    const float*   kn_w    = (const float*)d_in[12];

    float* out_ctx = (float*)d_out;
    float* out_k   = out_ctx + (size_t)Bb * Tt * Hh * HD;
    float* out_v   = out_k   + (size_t)Bb * Gg * SS * HD;

    float *q_raw, *k_raw, *v_raw, *qf, *ctx;
    cudaGetSymbolAddress((void**)&q_raw, g_q_raw);
    cudaGetSymbolAddress((void**)&k_raw, g_k_raw);
    cudaGetSymbolAddress((void**)&v_raw, g_v_raw);
    cudaGetSymbolAddress((void**)&qf,    g_q);
    cudaGetSymbolAddress((void**)&ctx,   g_ctx);

    // cache halves of k_full / v_full
    {
        int n4 = Bb * Gg * CACHEN * HD / 4;
        int blocks = (n4 + 255) / 256;
        copy_cache_kernel<<<blocks, 256>>>((const float4*)cache_k, (float4*)out_k);
        copy_cache_kernel<<<blocks, 256>>>((const float4*)cache_v, (float4*)out_v);
    }

    // projections (tf32 tensor cores)
    gemm_tf32<<<dim3(16, 16), 256>>>(x, q_w, q_raw, 2048, 2048, 2048);
    gemm_tf32<<<dim3(4, 16),  256>>>(x, k_w, k_raw, 2048, 512,  2048);
    gemm_tf32<<<dim3(4, 16),  256>>>(x, v_w, v_raw, 2048, 512,  2048);

    // RMSNorm + RoPE; K goes straight into k_full's new-token region
    norm_rope_kernel<<<Bb * Tt * Hh, 128>>>(q_raw, qn_w, cosT, sinT, pos, qf,    Hh, Tt, 0);
    norm_rope_kernel<<<Bb * Tt * Gg, 128>>>(k_raw, kn_w, cosT, sinT, pos, out_k, Gg, SS, CACHEN);

    // V into v_full's new-token region
    {
        int n = Bb * Tt * Gg * HD;
        scatter_v_kernel<<<(n + 255) / 256, 256>>>(v_raw, out_v);
    }

    // attention (tf32 tensor cores)
    size_t smem = (size_t)(128 * 132 + 64 * 132 + 64 * 136) * 4 + 128 * 64;
    cudaFuncSetAttribute(attn_tf32, cudaFuncAttributeMaxDynamicSharedMemorySize, (int)smem);
    attn_tf32<<<dim3(Tt / 128, Hh, Bb), 256, smem>>>(qf, out_k, out_v, mask, ctx);

    // output projection
    gemm_tf32<<<dim3(16, 16), 256>>>(ctx, o_w, out_ctx, 2048, 2048, 2048);
}

// round 4
// speedup vs baseline: 4.9124x; 1.2261x over previous
#include <cuda_runtime.h>
#include <stdint.h>

#define Bb 4
#define Tt 512
#define Hh 16
#define Gg 4
#define HD 128
#define CACHEN 3584
#define SS 4096

// Scratch (static device arrays; no allocation allowed)
__device__ float g_xr   [2048*2048];     // tf32-rounded x
__device__ float g_wqkv [2048*3072];     // tf32-rounded [q_w | k_w | v_w]
__device__ float g_owr  [2048*2048];     // tf32-rounded o_w
__device__ float g_qkv  [2048*3072];     // fused projection output [B*T, 3072]
__device__ float g_q    [Bb*Hh*Tt*HD];   // [B,H,T,HD]
__device__ float g_ctx  [Bb*Tt*Hh*HD];   // [B,T,H,HD] (tf32-rounded)

__device__ __forceinline__ unsigned f2t(float x) {
    unsigned r;
    asm("cvt.rna.tf32.f32 %0, %1;" : "=r"(r) : "f"(x));
    return r;
}

__device__ __forceinline__ void mma8(float* c,
    unsigned a0, unsigned a1, unsigned a2, unsigned a3,
    unsigned b0, unsigned b1)
{
    asm volatile(
        "mma.sync.aligned.m16n8k8.row.col.f32.tf32.tf32.f32 "
        "{%0,%1,%2,%3}, {%4,%5,%6,%7}, {%8,%9}, {%0,%1,%2,%3};"
        : "+f"(c[0]), "+f"(c[1]), "+f"(c[2]), "+f"(c[3])
        : "r"(a0), "r"(a1), "r"(a2), "r"(a3), "r"(b0), "r"(b1));
}

#define CPASYNC16(dst_sm, src_gm) \
    asm volatile("cp.async.cg.shared.global [%0], [%1], 16;\n" \
                 :: "r"(dst_sm), "l"(src_gm))

// ---------------------------------------------------------------------------
// Prep kernels: tf32-round inputs once so GEMM mainloop feeds raw bits to mma.
// ---------------------------------------------------------------------------
__global__ __launch_bounds__(256) void round_copy_kernel(
    const float4* __restrict__ src, float4* __restrict__ dst, int n4)
{
    int i = blockIdx.x * blockDim.x + threadIdx.x;
    if (i >= n4) return;
    float4 v = src[i];
    float4 o;
    o.x = __uint_as_float(f2t(v.x)); o.y = __uint_as_float(f2t(v.y));
    o.z = __uint_as_float(f2t(v.z)); o.w = __uint_as_float(f2t(v.w));
    dst[i] = o;
}

__global__ __launch_bounds__(256) void pack_wqkv_kernel(
    const float* __restrict__ qw, const float* __restrict__ kw,
    const float* __restrict__ vw, float* __restrict__ dst)
{
    int i = blockIdx.x * blockDim.x + threadIdx.x;   // over 2048*3072
    if (i >= 2048 * 3072) return;
    int k = i / 3072, c = i % 3072;
    float v;
    if (c < 2048)      v = qw[(size_t)k * 2048 + c];
    else if (c < 2560) v = kw[(size_t)k * 512 + (c - 2048)];
    else               v = vw[(size_t)k * 512 + (c - 2560)];
    dst[i] = __uint_as_float(f2t(v));
}

// ---------------------------------------------------------------------------
// tf32 GEMM, cp.async double-buffered. C[M,N] = A[M,K] @ B[K,N].
// Inputs MUST be pre-rounded to tf32. Block tile 128x128, BK=32, 256 thr.
// ---------------------------------------------------------------------------
__global__ __launch_bounds__(256, 2) void gemm_tf32_db(
    const float* __restrict__ A, const float* __restrict__ Bm,
    float* __restrict__ C, int M, int N, int K)
{
    extern __shared__ unsigned sm[];
    unsigned* As = sm;                    // 2 stages of [128][36]
    unsigned* Bs = sm + 2 * 128 * 36;     // 2 stages of [32][136]
    const int ASTG = 128 * 36, BSTG = 32 * 136;

    int tid = threadIdx.x, lane = tid & 31, warp = tid >> 5;
    int g = lane >> 2, tg = lane & 3;
    int m0 = blockIdx.y << 7, n0 = blockIdx.x << 7;
    int wm = (warp >> 2) << 6, wn = (warp & 3) << 5;

    float acc[4][4][4];
    #pragma unroll
    for (int i = 0; i < 4; i++)
        #pragma unroll
        for (int j = 0; j < 4; j++)
            #pragma unroll
            for (int e = 0; e < 4; e++) acc[i][j][e] = 0.0f;

    // cp.async chunk coordinates (4 x 16B per thread per operand per stage)
    int ar[4], ac[4], br[4], bc[4];
    #pragma unroll
    for (int t = 0; t < 4; t++) {
        int i = tid + t * 256;
        ar[t] = i >> 3;  ac[t] = (i & 7) << 2;
        br[t] = i >> 5;  bc[t] = (i & 31) << 2;
    }

    auto load_stage = [&](int k0, int s) {
        #pragma unroll
        for (int t = 0; t < 4; t++) {
            unsigned da = (unsigned)__cvta_generic_to_shared(
                &As[s * ASTG + ar[t] * 36 + ac[t]]);
            CPASYNC16(da, &A[(size_t)(m0 + ar[t]) * K + k0 + ac[t]]);
            unsigned db = (unsigned)__cvta_generic_to_shared(
                &Bs[s * BSTG + br[t] * 136 + bc[t]]);
            CPASYNC16(db, &Bm[(size_t)(k0 + br[t]) * N + n0 + bc[t]]);
        }
        asm volatile("cp.async.commit_group;\n");
    };

    int niter = K >> 5;
    load_stage(0, 0);

    for (int it = 0; it < niter; it++) {
        if (it + 1 < niter) {
            load_stage((it + 1) << 5, (it + 1) & 1);
            asm volatile("cp.async.wait_group 1;\n");
        } else {
            asm volatile("cp.async.wait_group 0;\n");
        }
        __syncthreads();

        const unsigned* Ab = As + (it & 1) * ASTG;
        const unsigned* Bbuf = Bs + (it & 1) * BSTG;
        #pragma unroll
        for (int ks = 0; ks < 32; ks += 8) {
            unsigned a[4][4];
            #pragma unroll
            for (int mt = 0; mt < 4; mt++) {
                int r = wm + mt * 16;
                a[mt][0] = Ab[(r + g) * 36 + ks + tg];
                a[mt][1] = Ab[(r + g + 8) * 36 + ks + tg];
                a[mt][2] = Ab[(r + g) * 36 + ks + tg + 4];
                a[mt][3] = Ab[(r + g + 8) * 36 + ks + tg + 4];
            }
            #pragma unroll
            for (int nt = 0; nt < 4; nt++) {
                unsigned b0 = Bbuf[(ks + tg) * 136 + wn + nt * 8 + g];
                unsigned b1 = Bbuf[(ks + tg + 4) * 136 + wn + nt * 8 + g];
                #pragma unroll
                for (int mt = 0; mt < 4; mt++)
                    mma8(acc[mt][nt], a[mt][0], a[mt][1], a[mt][2], a[mt][3], b0, b1);
            }
        }
        __syncthreads();
    }

    #pragma unroll
    for (int mt = 0; mt < 4; mt++)
        #pragma unroll
        for (int nt = 0; nt < 4; nt++) {
            int r0 = m0 + wm + mt * 16 + g;
            int c  = n0 + wn + nt * 8 + 2 * tg;
            float2 v0 = make_float2(acc[mt][nt][0], acc[mt][nt][1]);
            float2 v1 = make_float2(acc[mt][nt][2], acc[mt][nt][3]);
            *(float2*)&C[(size_t)r0 * N + c] = v0;
            *(float2*)&C[(size_t)(r0 + 8) * N + c] = v1;
        }
}

// ---------------------------------------------------------------------------
// Fused per-head RMSNorm + RoPE, reading from fused QKV buffer.
// raw row = bt (stride 3072), col = coloff + h*128 + d.
// ---------------------------------------------------------------------------
__global__ __launch_bounds__(128) void norm_rope_kernel(
    const float* __restrict__ raw, int coloff, const float* __restrict__ nw,
    const float* __restrict__ cosT, const float* __restrict__ sinT,
    const int* __restrict__ pos, float* __restrict__ out,
    int NH, int Tout, int toff)
{
    int idx = blockIdx.x;          // (b*T + t)*NH + h
    int h  = idx % NH;
    int bt = idx / NH;
    int t  = bt % Tt;
    int b  = bt / Tt;
    int d  = threadIdx.x;

    __shared__ float zn[128];
    __shared__ float red[4];

    float z = raw[(size_t)bt * 3072 + coloff + h * HD + d];
    float ss = z * z;
    #pragma unroll
    for (int o = 16; o; o >>= 1) ss += __shfl_xor_sync(0xffffffffu, ss, o);
    if ((d & 31) == 0) red[d >> 5] = ss;
    __syncthreads();
    float tot = red[0] + red[1] + red[2] + red[3];
    float r = rsqrtf(tot * (1.0f / 128.0f) + 1e-6f);
    float v = z * r * nw[d];
    zn[d] = v;
    __syncthreads();

    int p = pos[bt];
    float c = cosT[p * HD + d];
    float s = sinT[p * HD + d];
    float rot = (d < 64) ? -zn[d + 64] : zn[d - 64];
    float o = fmaf(v, c, rot * s);
    out[(((size_t)b * NH + h) * Tout + (toff + t)) * HD + d] = o;
}

// V scatter from fused buffer: v_full[b,g,CACHE+t,d] = qkv[bt*3072 + 2560 + g*128 + d]
__global__ __launch_bounds__(256) void scatter_v_kernel(
    const float* __restrict__ qkv, float* __restrict__ vf)
{
    int i = blockIdx.x * blockDim.x + threadIdx.x;
    const int n = Bb * Tt * Gg * HD;
    if (i >= n) return;
    int d = i & 127;
    int g = (i >> 7) & 3;
    int t = (i >> 9) % Tt;
    int b = i / (HD * Gg * Tt);
    int bt = b * Tt + t;
    vf[(((size_t)(b * Gg + g)) * SS + CACHEN + t) * HD + d] =
        qkv[(size_t)bt * 3072 + 2560 + g * HD + d];
}

__global__ __launch_bounds__(256) void copy_cache_kernel(
    const float4* __restrict__ src, float4* __restrict__ dst)
{
    int i = blockIdx.x * blockDim.x + threadIdx.x;
    const int per = CACHEN * HD / 4;
    const int n4  = Bb * Gg * per;
    if (i >= n4) return;
    int bg = i / per, r = i % per;
    dst[(size_t)bg * (SS * HD / 4) + r] = src[i];
}

// ---------------------------------------------------------------------------
// tf32 flash attention. grid=(T/128, H, B), 256 threads = 8 warps.
// ---------------------------------------------------------------------------
__global__ __launch_bounds__(256) void attn_tf32(
    const float* __restrict__ q, const float* __restrict__ kf,
    const float* __restrict__ vf, const uint8_t* __restrict__ mask,
    float* __restrict__ ctx)
{
    extern __shared__ char smraw[];
    unsigned* Qs = (unsigned*)smraw;         // [128][132]
    unsigned* Ks = Qs + 128 * 132;           // [64][132]
    unsigned* Vs = Ks + 64 * 132;            // [64][136]
    uint8_t*  Msk = (uint8_t*)(Vs + 64 * 136); // [128][64]

    int qt = blockIdx.x, h = blockIdx.y, b = blockIdx.z;
    int gh = h >> 2;
    int tid = threadIdx.x, lane = tid & 31, wq = tid >> 5;
    int g = lane >> 2, tg = lane & 3;
    const float scale = 0.08838834764831845f;

    const float* qb = q + (((size_t)b * Hh + h) * Tt + qt * 128) * HD;
    for (int i = tid; i < 4096; i += 256) {
        int r = i >> 5, cg = (i & 31) << 2;
        float4 v = *(const float4*)&qb[(size_t)r * HD + cg];
        uint4 u;
        u.x = f2t(v.x * scale); u.y = f2t(v.y * scale);
        u.z = f2t(v.z * scale); u.w = f2t(v.w * scale);
        *(uint4*)&Qs[r * 132 + cg] = u;
    }

    float oacc[16][4];
    #pragma unroll
    for (int nt = 0; nt < 16; nt++)
        #pragma unroll
        for (int e = 0; e < 4; e++) oacc[nt][e] = 0.0f;
    float m0r = -1e30f, m1r = -1e30f, l0 = 0.0f, l1 = 0.0f;

    const float* kb = kf + ((size_t)b * Gg + gh) * SS * HD;
    const float* vb = vf + ((size_t)b * Gg + gh) * SS * HD;
    const uint8_t* mb = mask + ((size_t)b * Tt + qt * 128) * SS;
    int qrow = wq * 16;

    for (int s0 = 0; s0 < SS; s0 += 64) {
        for (int i = tid; i < 2048; i += 256) {
            int r = i >> 5, cg = (i & 31) << 2;
            float4 kv = *(const float4*)&kb[(size_t)(s0 + r) * HD + cg];
            uint4 uk;
            uk.x = f2t(kv.x); uk.y = f2t(kv.y); uk.z = f2t(kv.z); uk.w = f2t(kv.w);
            *(uint4*)&Ks[r * 132 + cg] = uk;
            float4 vv = *(const float4*)&vb[(size_t)(s0 + r) * HD + cg];
            uint4 uv;
            uv.x = f2t(vv.x); uv.y = f2t(vv.y); uv.z = f2t(vv.z); uv.w = f2t(vv.w);
            *(uint4*)&Vs[r * 136 + cg] = uv;
        }
        for (int i = tid; i < 512; i += 256) {
            int r = i >> 2, c = (i & 3) << 4;
            *(uint4*)&Msk[r * 64 + c] = *(const uint4*)&mb[(size_t)r * SS + s0 + c];
        }
        __syncthreads();

        float sacc[8][4];
        #pragma unroll
        for (int nt = 0; nt < 8; nt++)
            #pragma unroll
            for (int e = 0; e < 4; e++) sacc[nt][e] = 0.0f;

        #pragma unroll
        for (int ks = 0; ks < 128; ks += 8) {
            unsigned a0 = Qs[(qrow + g) * 132 + ks + tg];
            unsigned a1 = Qs[(qrow + g + 8) * 132 + ks + tg];
            unsigned a2 = Qs[(qrow + g) * 132 + ks + tg + 4];
            unsigned a3 = Qs[(qrow + g + 8) * 132 + ks + tg + 4];
            #pragma unroll
            for (int nt = 0; nt < 8; nt++) {
                unsigned b0 = Ks[(nt * 8 + g) * 132 + ks + tg];
                unsigned b1 = Ks[(nt * 8 + g) * 132 + ks + tg + 4];
                mma8(sacc[nt], a0, a1, a2, a3, b0, b1);
            }
        }

        #pragma unroll
        for (int nt = 0; nt < 8; nt++) {
            unsigned short mm0 = *(const unsigned short*)&Msk[(qrow + g) * 64 + nt * 8 + 2 * tg];
            unsigned short mm1 = *(const unsigned short*)&Msk[(qrow + g + 8) * 64 + nt * 8 + 2 * tg];
            if (mm0 & 0x00FF) sacc[nt][0] = -1e30f;
            if (mm0 & 0xFF00) sacc[nt][1] = -1e30f;
            if (mm1 & 0x00FF) sacc[nt][2] = -1e30f;
            if (mm1 & 0xFF00) sacc[nt][3] = -1e30f;
        }

        float mx0 = -1e30f, mx1 = -1e30f;
        #pragma unroll
        for (int nt = 0; nt < 8; nt++) {
            mx0 = fmaxf(mx0, fmaxf(sacc[nt][0], sacc[nt][1]));
            mx1 = fmaxf(mx1, fmaxf(sacc[nt][2], sacc[nt][3]));
        }
        mx0 = fmaxf(mx0, __shfl_xor_sync(0xffffffffu, mx0, 1));
        mx0 = fmaxf(mx0, __shfl_xor_sync(0xffffffffu, mx0, 2));
        mx1 = fmaxf(mx1, __shfl_xor_sync(0xffffffffu, mx1, 1));
        mx1 = fmaxf(mx1, __shfl_xor_sync(0xffffffffu, mx1, 2));
        float mn0 = fmaxf(m0r, mx0), mn1 = fmaxf(m1r, mx1);
        float al0 = __expf(m0r - mn0), al1 = __expf(m1r - mn1);
        m0r = mn0; m1r = mn1;

        unsigned pu[8][4];
        float rs0 = 0.0f, rs1 = 0.0f;
        #pragma unroll
        for (int nt = 0; nt < 8; nt++) {
            float p0 = __expf(sacc[nt][0] - mn0);
            float p1 = __expf(sacc[nt][1] - mn0);
            float p2 = __expf(sacc[nt][2] - mn1);
            float p3 = __expf(sacc[nt][3] - mn1);
            rs0 += p0 + p1; rs1 += p2 + p3;
            pu[nt][0] = f2t(p0); pu[nt][1] = f2t(p1);
            pu[nt][2] = f2t(p2); pu[nt][3] = f2t(p3);
        }
        rs0 += __shfl_xor_sync(0xffffffffu, rs0, 1);
        rs0 += __shfl_xor_sync(0xffffffffu, rs0, 2);
        rs1 += __shfl_xor_sync(0xffffffffu, rs1, 1);
        rs1 += __shfl_xor_sync(0xffffffffu, rs1, 2);
        l0 = l0 * al0 + rs0;
        l1 = l1 * al1 + rs1;

        #pragma unroll
        for (int nt = 0; nt < 16; nt++) {
            oacc[nt][0] *= al0; oacc[nt][1] *= al0;
            oacc[nt][2] *= al1; oacc[nt][3] *= al1;
        }

        int base = lane & ~3, hs = tg >> 1, sel = tg & 1;
        #pragma unroll
        for (int kt = 0; kt < 8; kt++) {
            unsigned q0 = __shfl_sync(0xffffffffu, pu[kt][0], base + hs);
            unsigned q1 = __shfl_sync(0xffffffffu, pu[kt][1], base + hs);
            unsigned a0 = sel ? q1 : q0;
            unsigned q2 = __shfl_sync(0xffffffffu, pu[kt][0], base + hs + 2);
            unsigned q3 = __shfl_sync(0xffffffffu, pu[kt][1], base + hs + 2);
            unsigned a2 = sel ? q3 : q2;
            unsigned r0 = __shfl_sync(0xffffffffu, pu[kt][2], base + hs);
            unsigned r1 = __shfl_sync(0xffffffffu, pu[kt][3], base + hs);
            unsigned a1 = sel ? r1 : r0;
            unsigned r2 = __shfl_sync(0xffffffffu, pu[kt][2], base + hs + 2);
            unsigned r3 = __shfl_sync(0xffffffffu, pu[kt][3], base + hs + 2);
            unsigned a3 = sel ? r3 : r2;
            #pragma unroll
            for (int nt = 0; nt < 16; nt++) {
                unsigned b0 = Vs[(kt * 8 + tg) * 136 + nt * 8 + g];
                unsigned b1 = Vs[(kt * 8 + tg + 4) * 136 + nt * 8 + g];
                mma8(oacc[nt], a0, a1, a2, a3, b0, b1);
            }
        }
        __syncthreads();
    }

    // epilogue: ctx tf32-rounded so O-projection can feed mma directly
    float il0 = 1.0f / l0, il1 = 1.0f / l1;
    int tok0 = qt * 128 + qrow + g;
    #pragma unroll
    for (int nt = 0; nt < 16; nt++) {
        int d = nt * 8 + 2 * tg;
        float2 v0 = make_float2(__uint_as_float(f2t(oacc[nt][0] * il0)),
                                __uint_as_float(f2t(oacc[nt][1] * il0)));
        float2 v1 = make_float2(__uint_as_float(f2t(oacc[nt][2] * il1)),
                                __uint_as_float(f2t(oacc[nt][3] * il1)));
        *(float2*)&ctx[(((size_t)b * Tt + tok0) * Hh + h) * HD + d] = v0;
        *(float2*)&ctx[(((size_t)b * Tt + tok0 + 8) * Hh + h) * HD + d] = v1;
    }
}

// ---------------------------------------------------------------------------
extern "C" void kernel_launch(void* const* d_in, const int* in_sizes, int n_in,
                              void* d_out, int out_size)
{
    const float*   x       = (const float*)d_in[0];
    const uint8_t* mask    = (const uint8_t*)d_in[1];
    const float*   cosT    = (const float*)d_in[2];
    const float*   sinT    = (const float*)d_in[3];
    const int*     pos     = (const int*)d_in[4];
    const float*   cache_k = (const float*)d_in[5];
    const float*   cache_v = (const float*)d_in[6];
    const float*   q_w     = (const float*)d_in[7];
    const float*   k_w     = (const float*)d_in[8];
    const float*   v_w     = (const float*)d_in[9];
    const float*   o_w     = (const float*)d_in[10];
    const float*   qn_w    = (const float*)d_in[11];
    const float*   kn_w    = (const float*)d_in[12];

    float* out_ctx = (float*)d_out;
    float* out_k   = out_ctx + (size_t)Bb * Tt * Hh * HD;
    float* out_v   = out_k   + (size_t)Bb * Gg * SS * HD;

    float *xr, *wqkv, *owr, *qkv, *qf, *ctx;
    cudaGetSymbolAddress((void**)&xr,   g_xr);
    cudaGetSymbolAddress((void**)&wqkv, g_wqkv);
    cudaGetSymbolAddress((void**)&owr,  g_owr);
    cudaGetSymbolAddress((void**)&qkv,  g_qkv);
    cudaGetSymbolAddress((void**)&qf,   g_q);
    cudaGetSymbolAddress((void**)&ctx,  g_ctx);

    // cache halves of k_full / v_full
    {
        int n4 = Bb * Gg * CACHEN * HD / 4;
        int blocks = (n4 + 255) / 256;
        copy_cache_kernel<<<blocks, 256>>>((const float4*)cache_k, (float4*)out_k);
        copy_cache_kernel<<<blocks, 256>>>((const float4*)cache_v, (float4*)out_v);
    }

    // tf32 pre-rounding of GEMM operands
    {
        int n4x = 2048 * 2048 / 4;
        round_copy_kernel<<<(n4x + 255) / 256, 256>>>((const float4*)x, (float4*)xr, n4x);
        int n4o = 2048 * 2048 / 4;
        round_copy_kernel<<<(n4o + 255) / 256, 256>>>((const float4*)o_w, (float4*)owr, n4o);
        int nw = 2048 * 3072;
        pack_wqkv_kernel<<<(nw + 255) / 256, 256>>>(q_w, k_w, v_w, wqkv);
    }

    // fused QKV projection: [2048,2048] @ [2048,3072]
    size_t gsmem = (size_t)(2 * 128 * 36 + 2 * 32 * 136) * 4;
    cudaFuncSetAttribute(gemm_tf32_db, cudaFuncAttributeMaxDynamicSharedMemorySize, (int)gsmem);
    gemm_tf32_db<<<dim3(24, 16), 256, gsmem>>>(xr, wqkv, qkv, 2048, 3072, 2048);

    // RMSNorm + RoPE; K goes straight into k_full's new-token region
    norm_rope_kernel<<<Bb * Tt * Hh, 128>>>(qkv, 0,    qn_w, cosT, sinT, pos, qf,    Hh, Tt, 0);
    norm_rope_kernel<<<Bb * Tt * Gg, 128>>>(qkv, 2048, kn_w, cosT, sinT, pos, out_k, Gg, SS, CACHEN);

    // V into v_full's new-token region
    {
        int n = Bb * Tt * Gg * HD;
        scatter_v_kernel<<<(n + 255) / 256, 256>>>(qkv, out_v);
    }

    // attention (tf32 tensor cores)
    size_t smem = (size_t)(128 * 132 + 64 * 132 + 64 * 136) * 4 + 128 * 64;
    cudaFuncSetAttribute(attn_tf32, cudaFuncAttributeMaxDynamicSharedMemorySize, (int)smem);
    attn_tf32<<<dim3(Tt / 128, Hh, Bb), 256, smem>>>(qf, out_k, out_v, mask, ctx);

    // output projection
    gemm_tf32_db<<<dim3(16, 16), 256, gsmem>>>(ctx, owr, out_ctx, 2048, 2048, 2048);
}

// round 5
// speedup vs baseline: 5.6487x; 1.1499x over previous
#include <cuda_runtime.h>
#include <stdint.h>

#define Bb 4
#define Tt 512
#define Hh 16
#define Gg 4
#define HD 128
#define CACHEN 3584
#define SS 4096

// Scratch (static device arrays; no allocation allowed)
__device__ float g_xr   [2048*2048];     // tf32-rounded x
__device__ float g_wqkv [2048*3072];     // tf32-rounded [q_w | k_w | v_w]
__device__ float g_owr  [2048*2048];     // tf32-rounded o_w
__device__ float g_qkv  [2048*3072];     // fused projection output [B*T, 3072]
__device__ float g_q    [Bb*Hh*Tt*HD];   // [B,H,T,HD]
__device__ float g_ctx  [Bb*Tt*Hh*HD];   // [B,T,H,HD] (tf32-rounded)
__device__ float g_kt   [Bb*Gg*SS*HD];   // tf32-rounded k_full
__device__ float g_vt   [Bb*Gg*SS*HD];   // tf32-rounded v_full

__device__ __forceinline__ unsigned f2t(float x) {
    unsigned r;
    asm("cvt.rna.tf32.f32 %0, %1;" : "=r"(r) : "f"(x));
    return r;
}

__device__ __forceinline__ void mma8(float* c,
    unsigned a0, unsigned a1, unsigned a2, unsigned a3,
    unsigned b0, unsigned b1)
{
    asm volatile(
        "mma.sync.aligned.m16n8k8.row.col.f32.tf32.tf32.f32 "
        "{%0,%1,%2,%3}, {%4,%5,%6,%7}, {%8,%9}, {%0,%1,%2,%3};"
        : "+f"(c[0]), "+f"(c[1]), "+f"(c[2]), "+f"(c[3])
        : "r"(a0), "r"(a1), "r"(a2), "r"(a3), "r"(b0), "r"(b1));
}

#define CPASYNC16(dst_sm, src_gm) \
    asm volatile("cp.async.cg.shared.global [%0], [%1], 16;\n" \
                 :: "r"(dst_sm), "l"(src_gm))

// ---------------------------------------------------------------------------
// Prep kernels
// ---------------------------------------------------------------------------
__global__ __launch_bounds__(256) void round_copy_kernel(
    const float4* __restrict__ src, float4* __restrict__ dst, int n4)
{
    int i = blockIdx.x * blockDim.x + threadIdx.x;
    if (i >= n4) return;
    float4 v = src[i];
    float4 o;
    o.x = __uint_as_float(f2t(v.x)); o.y = __uint_as_float(f2t(v.y));
    o.z = __uint_as_float(f2t(v.z)); o.w = __uint_as_float(f2t(v.w));
    dst[i] = o;
}

__global__ __launch_bounds__(256) void pack_wqkv_kernel(
    const float* __restrict__ qw, const float* __restrict__ kw,
    const float* __restrict__ vw, float* __restrict__ dst)
{
    int i = blockIdx.x * blockDim.x + threadIdx.x;
    if (i >= 2048 * 3072) return;
    int k = i / 3072, c = i % 3072;
    float v;
    if (c < 2048)      v = qw[(size_t)k * 2048 + c];
    else if (c < 2560) v = kw[(size_t)k * 512 + (c - 2048)];
    else               v = vw[(size_t)k * 512 + (c - 2560)];
    dst[i] = __uint_as_float(f2t(v));
}

// ---------------------------------------------------------------------------
// tf32 GEMM, cp.async double-buffered (unchanged from round 4).
// ---------------------------------------------------------------------------
__global__ __launch_bounds__(256, 2) void gemm_tf32_db(
    const float* __restrict__ A, const float* __restrict__ Bm,
    float* __restrict__ C, int M, int N, int K)
{
    extern __shared__ unsigned sm[];
    unsigned* As = sm;                    // 2 stages of [128][36]
    unsigned* Bs = sm + 2 * 128 * 36;     // 2 stages of [32][136]
    const int ASTG = 128 * 36, BSTG = 32 * 136;

    int tid = threadIdx.x, lane = tid & 31, warp = tid >> 5;
    int g = lane >> 2, tg = lane & 3;
    int m0 = blockIdx.y << 7, n0 = blockIdx.x << 7;
    int wm = (warp >> 2) << 6, wn = (warp & 3) << 5;

    float acc[4][4][4];
    #pragma unroll
    for (int i = 0; i < 4; i++)
        #pragma unroll
        for (int j = 0; j < 4; j++)
            #pragma unroll
            for (int e = 0; e < 4; e++) acc[i][j][e] = 0.0f;

    int ar[4], ac[4], br[4], bc[4];
    #pragma unroll
    for (int t = 0; t < 4; t++) {
        int i = tid + t * 256;
        ar[t] = i >> 3;  ac[t] = (i & 7) << 2;
        br[t] = i >> 5;  bc[t] = (i & 31) << 2;
    }

    auto load_stage = [&](int k0, int s) {
        #pragma unroll
        for (int t = 0; t < 4; t++) {
            unsigned da = (unsigned)__cvta_generic_to_shared(
                &As[s * ASTG + ar[t] * 36 + ac[t]]);
            CPASYNC16(da, &A[(size_t)(m0 + ar[t]) * K + k0 + ac[t]]);
            unsigned db = (unsigned)__cvta_generic_to_shared(
                &Bs[s * BSTG + br[t] * 136 + bc[t]]);
            CPASYNC16(db, &Bm[(size_t)(k0 + br[t]) * N + n0 + bc[t]]);
        }
        asm volatile("cp.async.commit_group;\n");
    };

    int niter = K >> 5;
    load_stage(0, 0);

    for (int it = 0; it < niter; it++) {
        if (it + 1 < niter) {
            load_stage((it + 1) << 5, (it + 1) & 1);
            asm volatile("cp.async.wait_group 1;\n");
        } else {
            asm volatile("cp.async.wait_group 0;\n");
        }
        __syncthreads();

        const unsigned* Ab = As + (it & 1) * ASTG;
        const unsigned* Bbuf = Bs + (it & 1) * BSTG;
        #pragma unroll
        for (int ks = 0; ks < 32; ks += 8) {
            unsigned a[4][4];
            #pragma unroll
            for (int mt = 0; mt < 4; mt++) {
                int r = wm + mt * 16;
                a[mt][0] = Ab[(r + g) * 36 + ks + tg];
                a[mt][1] = Ab[(r + g + 8) * 36 + ks + tg];
                a[mt][2] = Ab[(r + g) * 36 + ks + tg + 4];
                a[mt][3] = Ab[(r + g + 8) * 36 + ks + tg + 4];
            }
            #pragma unroll
            for (int nt = 0; nt < 4; nt++) {
                unsigned b0 = Bbuf[(ks + tg) * 136 + wn + nt * 8 + g];
                unsigned b1 = Bbuf[(ks + tg + 4) * 136 + wn + nt * 8 + g];
                #pragma unroll
                for (int mt = 0; mt < 4; mt++)
                    mma8(acc[mt][nt], a[mt][0], a[mt][1], a[mt][2], a[mt][3], b0, b1);
            }
        }
        __syncthreads();
    }

    #pragma unroll
    for (int mt = 0; mt < 4; mt++)
        #pragma unroll
        for (int nt = 0; nt < 4; nt++) {
            int r0 = m0 + wm + mt * 16 + g;
            int c  = n0 + wn + nt * 8 + 2 * tg;
            float2 v0 = make_float2(acc[mt][nt][0], acc[mt][nt][1]);
            float2 v1 = make_float2(acc[mt][nt][2], acc[mt][nt][3]);
            *(float2*)&C[(size_t)r0 * N + c] = v0;
            *(float2*)&C[(size_t)(r0 + 8) * N + c] = v1;
        }
}

// ---------------------------------------------------------------------------
// Fused per-head RMSNorm + RoPE; optional tf32-rounded second output.
// ---------------------------------------------------------------------------
__global__ __launch_bounds__(128) void norm_rope_kernel(
    const float* __restrict__ raw, int coloff, const float* __restrict__ nw,
    const float* __restrict__ cosT, const float* __restrict__ sinT,
    const int* __restrict__ pos, float* __restrict__ out,
    float* __restrict__ outr, int NH, int Tout, int toff)
{
    int idx = blockIdx.x;          // (b*T + t)*NH + h
    int h  = idx % NH;
    int bt = idx / NH;
    int t  = bt % Tt;
    int b  = bt / Tt;
    int d  = threadIdx.x;

    __shared__ float zn[128];
    __shared__ float red[4];

    float z = raw[(size_t)bt * 3072 + coloff + h * HD + d];
    float ss = z * z;
    #pragma unroll
    for (int o = 16; o; o >>= 1) ss += __shfl_xor_sync(0xffffffffu, ss, o);
    if ((d & 31) == 0) red[d >> 5] = ss;
    __syncthreads();
    float tot = red[0] + red[1] + red[2] + red[3];
    float r = rsqrtf(tot * (1.0f / 128.0f) + 1e-6f);
    float v = z * r * nw[d];
    zn[d] = v;
    __syncthreads();

    int p = pos[bt];
    float c = cosT[p * HD + d];
    float s = sinT[p * HD + d];
    float rot = (d < 64) ? -zn[d + 64] : zn[d - 64];
    float o = fmaf(v, c, rot * s);
    size_t oi = (((size_t)b * NH + h) * Tout + (toff + t)) * HD + d;
    out[oi] = o;
    if (outr) outr[oi] = __uint_as_float(f2t(o));
}

// V scatter: exact into v_full, rounded into v_tf32 scratch
__global__ __launch_bounds__(256) void scatter_v_kernel(
    const float* __restrict__ qkv, float* __restrict__ vf,
    float* __restrict__ vr)
{
    int i = blockIdx.x * blockDim.x + threadIdx.x;
    const int n = Bb * Tt * Gg * HD;
    if (i >= n) return;
    int d = i & 127;
    int g = (i >> 7) & 3;
    int t = (i >> 9) % Tt;
    int b = i / (HD * Gg * Tt);
    int bt = b * Tt + t;
    float v = qkv[(size_t)bt * 3072 + 2560 + g * HD + d];
    size_t oi = (((size_t)(b * Gg + g)) * SS + CACHEN + t) * HD + d;
    vf[oi] = v;
    vr[oi] = __uint_as_float(f2t(v));
}

// Cache copy: exact + rounded
__global__ __launch_bounds__(256) void copy_cache_kernel(
    const float4* __restrict__ src, float4* __restrict__ dst,
    float4* __restrict__ dstr)
{
    int i = blockIdx.x * blockDim.x + threadIdx.x;
    const int per = CACHEN * HD / 4;
    const int n4  = Bb * Gg * per;
    if (i >= n4) return;
    int bg = i / per, r = i % per;
    size_t oi = (size_t)bg * (SS * HD / 4) + r;
    float4 v = src[i];
    dst[oi] = v;
    float4 o;
    o.x = __uint_as_float(f2t(v.x)); o.y = __uint_as_float(f2t(v.y));
    o.z = __uint_as_float(f2t(v.z)); o.w = __uint_as_float(f2t(v.w));
    dstr[oi] = o;
}

// ---------------------------------------------------------------------------
// tf32 flash attention, cp.async double-buffered K/V/mask from pre-rounded
// scratch. grid=(T/128, H, B), 256 threads = 8 warps, 1 CTA/SM (227KB smem).
// ---------------------------------------------------------------------------
__global__ __launch_bounds__(256) void attn_tf32(
    const float* __restrict__ q, const float* __restrict__ kt,
    const float* __restrict__ vt, const uint8_t* __restrict__ mask,
    float* __restrict__ ctx)
{
    extern __shared__ char smraw[];
    unsigned* Qs = (unsigned*)smraw;              // [128][132]
    unsigned* Ks = Qs + 128 * 132;                // 2 x [64][140]
    unsigned* Vs = Ks + 2 * 64 * 140;             // 2 x [64][140]
    uint8_t*  Msk = (uint8_t*)(Vs + 2 * 64 * 140);// 2 x [128][64]
    const int KSTG = 64 * 140;

    int qt = blockIdx.x, h = blockIdx.y, b = blockIdx.z;
    int gh = h >> 2;
    int tid = threadIdx.x, lane = tid & 31, wq = tid >> 5;
    int g = lane >> 2, tg = lane & 3;
    const float scale = 0.08838834764831845f;

    const float* kb = kt + ((size_t)b * Gg + gh) * SS * HD;
    const float* vb = vt + ((size_t)b * Gg + gh) * SS * HD;
    const uint8_t* mb = mask + ((size_t)b * Tt + qt * 128) * SS;

    auto load_stage = [&](int ti, int s) {
        const float* kbt = kb + (size_t)ti * 64 * HD;
        const float* vbt = vb + (size_t)ti * 64 * HD;
        #pragma unroll
        for (int t = 0; t < 8; t++) {
            int c = tid + t * 256;           // 0..2047 chunks of 4 floats
            int row = c >> 5, col4 = (c & 31) << 2;
            unsigned dk = (unsigned)__cvta_generic_to_shared(
                &Ks[s * KSTG + row * 140 + col4]);
            CPASYNC16(dk, kbt + row * HD + col4);
            unsigned dv = (unsigned)__cvta_generic_to_shared(
                &Vs[s * KSTG + row * 140 + col4]);
            CPASYNC16(dv, vbt + row * HD + col4);
        }
        #pragma unroll
        for (int t = 0; t < 2; t++) {
            int c = tid + t * 256;           // 0..511 chunks of 16B
            int row = c >> 2, c16 = (c & 3) << 4;
            unsigned dm = (unsigned)__cvta_generic_to_shared(
                &Msk[s * 8192 + row * 64 + c16]);
            CPASYNC16(dm, mb + (size_t)row * SS + ti * 64 + c16);
        }
        asm volatile("cp.async.commit_group;\n");
    };

    // Q tile load + scale + tf32 round (once)
    const float* qb = q + (((size_t)b * Hh + h) * Tt + qt * 128) * HD;
    for (int i = tid; i < 4096; i += 256) {
        int r = i >> 5, cg = (i & 31) << 2;
        float4 v = *(const float4*)&qb[(size_t)r * HD + cg];
        uint4 u;
        u.x = f2t(v.x * scale); u.y = f2t(v.y * scale);
        u.z = f2t(v.z * scale); u.w = f2t(v.w * scale);
        *(uint4*)&Qs[r * 132 + cg] = u;
    }

    float oacc[16][4];
    #pragma unroll
    for (int nt = 0; nt < 16; nt++)
        #pragma unroll
        for (int e = 0; e < 4; e++) oacc[nt][e] = 0.0f;
    float m0r = -1e30f, m1r = -1e30f, l0 = 0.0f, l1 = 0.0f;
    int qrow = wq * 16;

    load_stage(0, 0);

    const int NT = SS / 64;
    for (int ti = 0; ti < NT; ti++) {
        if (ti + 1 < NT) {
            load_stage(ti + 1, (ti + 1) & 1);
            asm volatile("cp.async.wait_group 1;\n");
        } else {
            asm volatile("cp.async.wait_group 0;\n");
        }
        __syncthreads();

        const unsigned* Kb = Ks + (ti & 1) * KSTG;
        const unsigned* Vb = Vs + (ti & 1) * KSTG;
        const uint8_t*  Mb = Msk + (ti & 1) * 8192;

        float sacc[8][4];
        #pragma unroll
        for (int nt = 0; nt < 8; nt++)
            #pragma unroll
            for (int e = 0; e < 4; e++) sacc[nt][e] = 0.0f;

        #pragma unroll
        for (int ks = 0; ks < 128; ks += 8) {
            unsigned a0 = Qs[(qrow + g) * 132 + ks + tg];
            unsigned a1 = Qs[(qrow + g + 8) * 132 + ks + tg];
            unsigned a2 = Qs[(qrow + g) * 132 + ks + tg + 4];
            unsigned a3 = Qs[(qrow + g + 8) * 132 + ks + tg + 4];
            #pragma unroll
            for (int nt = 0; nt < 8; nt++) {
                unsigned b0 = Kb[(nt * 8 + g) * 140 + ks + tg];
                unsigned b1 = Kb[(nt * 8 + g) * 140 + ks + tg + 4];
                mma8(sacc[nt], a0, a1, a2, a3, b0, b1);
            }
        }

        #pragma unroll
        for (int nt = 0; nt < 8; nt++) {
            unsigned short mm0 = *(const unsigned short*)&Mb[(qrow + g) * 64 + nt * 8 + 2 * tg];
            unsigned short mm1 = *(const unsigned short*)&Mb[(qrow + g + 8) * 64 + nt * 8 + 2 * tg];
            if (mm0 & 0x00FF) sacc[nt][0] = -1e30f;
            if (mm0 & 0xFF00) sacc[nt][1] = -1e30f;
            if (mm1 & 0x00FF) sacc[nt][2] = -1e30f;
            if (mm1 & 0xFF00) sacc[nt][3] = -1e30f;
        }

        float mx0 = -1e30f, mx1 = -1e30f;
        #pragma unroll
        for (int nt = 0; nt < 8; nt++) {
            mx0 = fmaxf(mx0, fmaxf(sacc[nt][0], sacc[nt][1]));
            mx1 = fmaxf(mx1, fmaxf(sacc[nt][2], sacc[nt][3]));
        }
        mx0 = fmaxf(mx0, __shfl_xor_sync(0xffffffffu, mx0, 1));
        mx0 = fmaxf(mx0, __shfl_xor_sync(0xffffffffu, mx0, 2));
        mx1 = fmaxf(mx1, __shfl_xor_sync(0xffffffffu, mx1, 1));
        mx1 = fmaxf(mx1, __shfl_xor_sync(0xffffffffu, mx1, 2));
        float mn0 = fmaxf(m0r, mx0), mn1 = fmaxf(m1r, mx1);
        float al0 = __expf(m0r - mn0), al1 = __expf(m1r - mn1);
        m0r = mn0; m1r = mn1;

        unsigned pu[8][4];
        float rs0 = 0.0f, rs1 = 0.0f;
        #pragma unroll
        for (int nt = 0; nt < 8; nt++) {
            float p0 = __expf(sacc[nt][0] - mn0);
            float p1 = __expf(sacc[nt][1] - mn0);
            float p2 = __expf(sacc[nt][2] - mn1);
            float p3 = __expf(sacc[nt][3] - mn1);
            rs0 += p0 + p1; rs1 += p2 + p3;
            pu[nt][0] = f2t(p0); pu[nt][1] = f2t(p1);
            pu[nt][2] = f2t(p2); pu[nt][3] = f2t(p3);
        }
        rs0 += __shfl_xor_sync(0xffffffffu, rs0, 1);
        rs0 += __shfl_xor_sync(0xffffffffu, rs0, 2);
        rs1 += __shfl_xor_sync(0xffffffffu, rs1, 1);
        rs1 += __shfl_xor_sync(0xffffffffu, rs1, 2);
        l0 = l0 * al0 + rs0;
        l1 = l1 * al1 + rs1;

        #pragma unroll
        for (int nt = 0; nt < 16; nt++) {
            oacc[nt][0] *= al0; oacc[nt][1] *= al0;
            oacc[nt][2] *= al1; oacc[nt][3] *= al1;
        }

        int base = lane & ~3, hs = tg >> 1, sel = tg & 1;
        #pragma unroll
        for (int kt2 = 0; kt2 < 8; kt2++) {
            unsigned q0 = __shfl_sync(0xffffffffu, pu[kt2][0], base + hs);
            unsigned q1 = __shfl_sync(0xffffffffu, pu[kt2][1], base + hs);
            unsigned a0 = sel ? q1 : q0;
            unsigned q2 = __shfl_sync(0xffffffffu, pu[kt2][0], base + hs + 2);
            unsigned q3 = __shfl_sync(0xffffffffu, pu[kt2][1], base + hs + 2);
            unsigned a2 = sel ? q3 : q2;
            unsigned r0 = __shfl_sync(0xffffffffu, pu[kt2][2], base + hs);
            unsigned r1 = __shfl_sync(0xffffffffu, pu[kt2][3], base + hs);
            unsigned a1 = sel ? r1 : r0;
            unsigned r2 = __shfl_sync(0xffffffffu, pu[kt2][2], base + hs + 2);
            unsigned r3 = __shfl_sync(0xffffffffu, pu[kt2][3], base + hs + 2);
            unsigned a3 = sel ? r3 : r2;
            #pragma unroll
            for (int nt = 0; nt < 16; nt++) {
                unsigned b0 = Vb[(kt2 * 8 + tg) * 140 + nt * 8 + g];
                unsigned b1 = Vb[(kt2 * 8 + tg + 4) * 140 + nt * 8 + g];
                mma8(oacc[nt], a0, a1, a2, a3, b0, b1);
            }
        }
        __syncthreads();
    }

    // epilogue: ctx tf32-rounded so O-projection can feed mma directly
    float il0 = 1.0f / l0, il1 = 1.0f / l1;
    int tok0 = qt * 128 + qrow + g;
    #pragma unroll
    for (int nt = 0; nt < 16; nt++) {
        int d = nt * 8 + 2 * tg;
        float2 v0 = make_float2(__uint_as_float(f2t(oacc[nt][0] * il0)),
                                __uint_as_float(f2t(oacc[nt][1] * il0)));
        float2 v1 = make_float2(__uint_as_float(f2t(oacc[nt][2] * il1)),
                                __uint_as_float(f2t(oacc[nt][3] * il1)));
        *(float2*)&ctx[(((size_t)b * Tt + tok0) * Hh + h) * HD + d] = v0;
        *(float2*)&ctx[(((size_t)b * Tt + tok0 + 8) * Hh + h) * HD + d] = v1;
    }
}

// ---------------------------------------------------------------------------
extern "C" void kernel_launch(void* const* d_in, const int* in_sizes, int n_in,
                              void* d_out, int out_size)
{
    const float*   x       = (const float*)d_in[0];
    const uint8_t* mask    = (const uint8_t*)d_in[1];
    const float*   cosT    = (const float*)d_in[2];
    const float*   sinT    = (const float*)d_in[3];
    const int*     pos     = (const int*)d_in[4];
    const float*   cache_k = (const float*)d_in[5];
    const float*   cache_v = (const float*)d_in[6];
    const float*   q_w     = (const float*)d_in[7];
    const float*   k_w     = (const float*)d_in[8];
    const float*   v_w     = (const float*)d_in[9];
    const float*   o_w     = (const float*)d_in[10];
    const float*   qn_w    = (const float*)d_in[11];
    const float*   kn_w    = (const float*)d_in[12];

    float* out_ctx = (float*)d_out;
    float* out_k   = out_ctx + (size_t)Bb * Tt * Hh * HD;
    float* out_v   = out_k   + (size_t)Bb * Gg * SS * HD;

    float *xr, *wqkv, *owr, *qkv, *qf, *ctx, *ktr, *vtr;
    cudaGetSymbolAddress((void**)&xr,   g_xr);
    cudaGetSymbolAddress((void**)&wqkv, g_wqkv);
    cudaGetSymbolAddress((void**)&owr,  g_owr);
    cudaGetSymbolAddress((void**)&qkv,  g_qkv);
    cudaGetSymbolAddress((void**)&qf,   g_q);
    cudaGetSymbolAddress((void**)&ctx,  g_ctx);
    cudaGetSymbolAddress((void**)&ktr,  g_kt);
    cudaGetSymbolAddress((void**)&vtr,  g_vt);

    // cache halves of k_full / v_full (exact + tf32-rounded scratch)
    {
        int n4 = Bb * Gg * CACHEN * HD / 4;
        int blocks = (n4 + 255) / 256;
        copy_cache_kernel<<<blocks, 256>>>((const float4*)cache_k, (float4*)out_k, (float4*)ktr);
        copy_cache_kernel<<<blocks, 256>>>((const float4*)cache_v, (float4*)out_v, (float4*)vtr);
    }

    // tf32 pre-rounding of GEMM operands
    {
        int n4x = 2048 * 2048 / 4;
        round_copy_kernel<<<(n4x + 255) / 256, 256>>>((const float4*)x, (float4*)xr, n4x);
        int n4o = 2048 * 2048 / 4;
        round_copy_kernel<<<(n4o + 255) / 256, 256>>>((const float4*)o_w, (float4*)owr, n4o);
        int nw = 2048 * 3072;
        pack_wqkv_kernel<<<(nw + 255) / 256, 256>>>(q_w, k_w, v_w, wqkv);
    }

    // fused QKV projection: [2048,2048] @ [2048,3072]
    size_t gsmem = (size_t)(2 * 128 * 36 + 2 * 32 * 136) * 4;
    cudaFuncSetAttribute(gemm_tf32_db, cudaFuncAttributeMaxDynamicSharedMemorySize, (int)gsmem);
    gemm_tf32_db<<<dim3(24, 16), 256, gsmem>>>(xr, wqkv, qkv, 2048, 3072, 2048);

    // RMSNorm + RoPE; K into k_full (exact) + k_tf32 scratch (rounded)
    norm_rope_kernel<<<Bb * Tt * Hh, 128>>>(qkv, 0,    qn_w, cosT, sinT, pos, qf,    nullptr, Hh, Tt, 0);
    norm_rope_kernel<<<Bb * Tt * Gg, 128>>>(qkv, 2048, kn_w, cosT, sinT, pos, out_k, ktr,     Gg, SS, CACHEN);

    // V into v_full (exact) + v_tf32 scratch (rounded)
    {
        int n = Bb * Tt * Gg * HD;
        scatter_v_kernel<<<(n + 255) / 256, 256>>>(qkv, out_v, vtr);
    }

    // attention (tf32 tensor cores, cp.async double-buffered)
    size_t smem = (size_t)(128 * 132 + 2 * 64 * 140 * 2) * 4 + 2 * 128 * 64;
    cudaFuncSetAttribute(attn_tf32, cudaFuncAttributeMaxDynamicSharedMemorySize, (int)smem);
    attn_tf32<<<dim3(Tt / 128, Hh, Bb), 256, smem>>>(qf, ktr, vtr, mask, ctx);

    // output projection
    gemm_tf32_db<<<dim3(16, 16), 256, gsmem>>>(ctx, owr, out_ctx, 2048, 2048, 2048);
}

// round 6
// speedup vs baseline: 6.4021x; 1.1334x over previous
#include <cuda_runtime.h>
#include <stdint.h>

#define Bb 4
#define Tt 512
#define Hh 16
#define Gg 4
#define HD 128
#define CACHEN 3584
#define SS 4096

// Scratch (static device arrays; no allocation allowed)
__device__ float g_xr   [2048*2048];     // tf32-rounded x
__device__ float g_wqkv [2048*3072];     // tf32-rounded [q_w | k_w | v_w]
__device__ float g_owr  [2048*2048];     // tf32-rounded o_w
__device__ float g_qkv  [2048*3072];     // fused projection output [B*T, 3072]
__device__ float g_q    [Bb*Hh*Tt*HD];   // [B,H,T,HD]
__device__ float g_ctx  [Bb*Tt*Hh*HD];   // [B,T,H,HD] (tf32-rounded)
__device__ float g_kt   [Bb*Gg*SS*HD];   // tf32-rounded k_full [B,G,S,HD]
__device__ float g_vt   [Bb*Gg*HD*SS];   // tf32-rounded v_full TRANSPOSED [B,G,HD,S]

__device__ __forceinline__ unsigned f2t(float x) {
    unsigned r;
    asm("cvt.rna.tf32.f32 %0, %1;" : "=r"(r) : "f"(x));
    return r;
}

__device__ __forceinline__ void mma8(float* c,
    unsigned a0, unsigned a1, unsigned a2, unsigned a3,
    unsigned b0, unsigned b1)
{
    asm volatile(
        "mma.sync.aligned.m16n8k8.row.col.f32.tf32.tf32.f32 "
        "{%0,%1,%2,%3}, {%4,%5,%6,%7}, {%8,%9}, {%0,%1,%2,%3};"
        : "+f"(c[0]), "+f"(c[1]), "+f"(c[2]), "+f"(c[3])
        : "r"(a0), "r"(a1), "r"(a2), "r"(a3), "r"(b0), "r"(b1));
}

#define CPASYNC16(dst_sm, src_gm) \
    asm volatile("cp.async.cg.shared.global [%0], [%1], 16;\n" \
                 :: "r"(dst_sm), "l"(src_gm))

// ---------------------------------------------------------------------------
// Prep kernels
// ---------------------------------------------------------------------------
__global__ __launch_bounds__(256) void round_copy_kernel(
    const float4* __restrict__ src, float4* __restrict__ dst, int n4)
{
    int i = blockIdx.x * blockDim.x + threadIdx.x;
    if (i >= n4) return;
    float4 v = src[i];
    float4 o;
    o.x = __uint_as_float(f2t(v.x)); o.y = __uint_as_float(f2t(v.y));
    o.z = __uint_as_float(f2t(v.z)); o.w = __uint_as_float(f2t(v.w));
    dst[i] = o;
}

__global__ __launch_bounds__(256) void pack_wqkv_kernel(
    const float* __restrict__ qw, const float* __restrict__ kw,
    const float* __restrict__ vw, float* __restrict__ dst)
{
    int i = blockIdx.x * blockDim.x + threadIdx.x;
    if (i >= 2048 * 3072) return;
    int k = i / 3072, c = i % 3072;
    float v;
    if (c < 2048)      v = qw[(size_t)k * 2048 + c];
    else if (c < 2560) v = kw[(size_t)k * 512 + (c - 2048)];
    else               v = vw[(size_t)k * 512 + (c - 2560)];
    dst[i] = __uint_as_float(f2t(v));
}

// Tiled transpose + tf32 round: [bg][s][d] -> [bg][d][s]
__global__ __launch_bounds__(256) void transpose_round_kernel(
    const float* __restrict__ src, float* __restrict__ dst)
{
    __shared__ float tile[32][33];
    int bg = blockIdx.z;
    int s0 = blockIdx.x << 5, d0 = blockIdx.y << 5;
    const float* s = src + (size_t)bg * SS * HD;
    float* d = dst + (size_t)bg * HD * SS;
    int tx = threadIdx.x & 31, ty = threadIdx.x >> 5;   // 32 x 8
    #pragma unroll
    for (int r = 0; r < 32; r += 8)
        tile[ty + r][tx] = s[(size_t)(s0 + ty + r) * HD + d0 + tx];
    __syncthreads();
    #pragma unroll
    for (int r = 0; r < 32; r += 8)
        d[(size_t)(d0 + ty + r) * SS + s0 + tx] =
            __uint_as_float(f2t(tile[tx][ty + r]));
}

// ---------------------------------------------------------------------------
// tf32 GEMM, cp.async double-buffered, uint2 A-fragments (slot-remapped).
// C[M,N] = A[M,K] @ B[K,N]. Block 128x128, BK=32, 256 thr, 2 CTA/SM.
// ---------------------------------------------------------------------------
__global__ __launch_bounds__(256, 2) void gemm_tf32_db(
    const float* __restrict__ A, const float* __restrict__ Bm,
    float* __restrict__ C, int M, int N, int K)
{
    extern __shared__ unsigned sm[];
    unsigned* As = sm;                    // 2 stages of [128][40]
    unsigned* Bs = sm + 2 * 128 * 40;     // 2 stages of [32][132]
    const int ASTG = 128 * 40, BSTG = 32 * 132;

    int tid = threadIdx.x, lane = tid & 31, warp = tid >> 5;
    int g = lane >> 2, tg = lane & 3;
    int m0 = blockIdx.y << 7, n0 = blockIdx.x << 7;
    int wm = (warp >> 2) << 6, wn = (warp & 3) << 5;

    float acc[4][4][4];
    #pragma unroll
    for (int i = 0; i < 4; i++)
        #pragma unroll
        for (int j = 0; j < 4; j++)
            #pragma unroll
            for (int e = 0; e < 4; e++) acc[i][j][e] = 0.0f;

    int ar[4], ac[4], br[4], bc[4];
    #pragma unroll
    for (int t = 0; t < 4; t++) {
        int i = tid + t * 256;
        ar[t] = i >> 3;  ac[t] = (i & 7) << 2;
        br[t] = i >> 5;  bc[t] = (i & 31) << 2;
    }

    auto load_stage = [&](int k0, int s) {
        #pragma unroll
        for (int t = 0; t < 4; t++) {
            unsigned da = (unsigned)__cvta_generic_to_shared(
                &As[s * ASTG + ar[t] * 40 + ac[t]]);
            CPASYNC16(da, &A[(size_t)(m0 + ar[t]) * K + k0 + ac[t]]);
            unsigned db = (unsigned)__cvta_generic_to_shared(
                &Bs[s * BSTG + br[t] * 132 + bc[t]]);
            CPASYNC16(db, &Bm[(size_t)(k0 + br[t]) * N + n0 + bc[t]]);
        }
        asm volatile("cp.async.commit_group;\n");
    };

    int niter = K >> 5;
    load_stage(0, 0);

    for (int it = 0; it < niter; it++) {
        if (it + 1 < niter) {
            load_stage((it + 1) << 5, (it + 1) & 1);
            asm volatile("cp.async.wait_group 1;\n");
        } else {
            asm volatile("cp.async.wait_group 0;\n");
        }
        __syncthreads();

        const unsigned* Ab = As + (it & 1) * ASTG;
        const unsigned* Bbuf = Bs + (it & 1) * BSTG;
        #pragma unroll
        for (int ks = 0; ks < 32; ks += 8) {
            // slot remap: k-slot tg <- col ks+2tg, slot tg+4 <- col ks+2tg+1
            uint2 alo[4], ahi[4];
            #pragma unroll
            for (int mt = 0; mt < 4; mt++) {
                int r = wm + mt * 16;
                alo[mt] = *(const uint2*)&Ab[(r + g) * 40 + ks + 2 * tg];
                ahi[mt] = *(const uint2*)&Ab[(r + g + 8) * 40 + ks + 2 * tg];
            }
            #pragma unroll
            for (int nt = 0; nt < 4; nt++) {
                unsigned b0 = Bbuf[(ks + 2 * tg) * 132 + wn + nt * 8 + g];
                unsigned b1 = Bbuf[(ks + 2 * tg + 1) * 132 + wn + nt * 8 + g];
                #pragma unroll
                for (int mt = 0; mt < 4; mt++)
                    mma8(acc[mt][nt], alo[mt].x, ahi[mt].x, alo[mt].y, ahi[mt].y, b0, b1);
            }
        }
        __syncthreads();
    }

    #pragma unroll
    for (int mt = 0; mt < 4; mt++)
        #pragma unroll
        for (int nt = 0; nt < 4; nt++) {
            int r0 = m0 + wm + mt * 16 + g;
            int c  = n0 + wn + nt * 8 + 2 * tg;
            float2 v0 = make_float2(acc[mt][nt][0], acc[mt][nt][1]);
            float2 v1 = make_float2(acc[mt][nt][2], acc[mt][nt][3]);
            *(float2*)&C[(size_t)r0 * N + c] = v0;
            *(float2*)&C[(size_t)(r0 + 8) * N + c] = v1;
        }
}

// ---------------------------------------------------------------------------
// Fused per-head RMSNorm + RoPE; optional tf32-rounded second output.
// ---------------------------------------------------------------------------
__global__ __launch_bounds__(128) void norm_rope_kernel(
    const float* __restrict__ raw, int coloff, const float* __restrict__ nw,
    const float* __restrict__ cosT, const float* __restrict__ sinT,
    const int* __restrict__ pos, float* __restrict__ out,
    float* __restrict__ outr, int NH, int Tout, int toff)
{
    int idx = blockIdx.x;          // (b*T + t)*NH + h
    int h  = idx % NH;
    int bt = idx / NH;
    int t  = bt % Tt;
    int b  = bt / Tt;
    int d  = threadIdx.x;

    __shared__ float zn[128];
    __shared__ float red[4];

    float z = raw[(size_t)bt * 3072 + coloff + h * HD + d];
    float ss = z * z;
    #pragma unroll
    for (int o = 16; o; o >>= 1) ss += __shfl_xor_sync(0xffffffffu, ss, o);
    if ((d & 31) == 0) red[d >> 5] = ss;
    __syncthreads();
    float tot = red[0] + red[1] + red[2] + red[3];
    float r = rsqrtf(tot * (1.0f / 128.0f) + 1e-6f);
    float v = z * r * nw[d];
    zn[d] = v;
    __syncthreads();

    int p = pos[bt];
    float c = cosT[p * HD + d];
    float s = sinT[p * HD + d];
    float rot = (d < 64) ? -zn[d + 64] : zn[d - 64];
    float o = fmaf(v, c, rot * s);
    size_t oi = (((size_t)b * NH + h) * Tout + (toff + t)) * HD + d;
    out[oi] = o;
    if (outr) outr[oi] = __uint_as_float(f2t(o));
}

// V scatter: exact into v_full only (rounded+transposed copy made later)
__global__ __launch_bounds__(256) void scatter_v_kernel(
    const float* __restrict__ qkv, float* __restrict__ vf)
{
    int i = blockIdx.x * blockDim.x + threadIdx.x;
    const int n = Bb * Tt * Gg * HD;
    if (i >= n) return;
    int d = i & 127;
    int g = (i >> 7) & 3;
    int t = (i >> 9) % Tt;
    int b = i / (HD * Gg * Tt);
    int bt = b * Tt + t;
    vf[(((size_t)(b * Gg + g)) * SS + CACHEN + t) * HD + d] =
        qkv[(size_t)bt * 3072 + 2560 + g * HD + d];
}

// Cache copy: exact + optional rounded
__global__ __launch_bounds__(256) void copy_cache_kernel(
    const float4* __restrict__ src, float4* __restrict__ dst,
    float4* __restrict__ dstr)
{
    int i = blockIdx.x * blockDim.x + threadIdx.x;
    const int per = CACHEN * HD / 4;
    const int n4  = Bb * Gg * per;
    if (i >= n4) return;
    int bg = i / per, r = i % per;
    size_t oi = (size_t)bg * (SS * HD / 4) + r;
    float4 v = src[i];
    dst[oi] = v;
    if (dstr) {
        float4 o;
        o.x = __uint_as_float(f2t(v.x)); o.y = __uint_as_float(f2t(v.y));
        o.z = __uint_as_float(f2t(v.z)); o.w = __uint_as_float(f2t(v.w));
        dstr[oi] = o;
    }
}

// ---------------------------------------------------------------------------
// tf32 flash attention, cp.async double-buffered, shuffle-free PV phase.
// K scratch [B,G,S,HD]; V scratch TRANSPOSED [B,G,HD,S] so S-output fragments
// feed PV directly. grid=(T/128, H, B), 256 threads, 229KB smem, 1 CTA/SM.
// ---------------------------------------------------------------------------
__global__ __launch_bounds__(256) void attn_tf32(
    const float* __restrict__ q, const float* __restrict__ kt,
    const float* __restrict__ vt, const uint8_t* __restrict__ mask,
    float* __restrict__ ctx)
{
    extern __shared__ char smraw[];
    unsigned* Qs = (unsigned*)smraw;               // [128][136]
    unsigned* Ks = Qs + 128 * 136;                 // 2 x [64 key][136]
    unsigned* Vs = Ks + 2 * 64 * 136;              // 2 x [128 d][72]
    uint8_t*  Msk = (uint8_t*)(Vs + 2 * 128 * 72); // 2 x [128][64]
    const int KSTG = 64 * 136, VSTG = 128 * 72;

    int qt = blockIdx.x, h = blockIdx.y, b = blockIdx.z;
    int gh = h >> 2;
    int tid = threadIdx.x, lane = tid & 31, wq = tid >> 5;
    int g = lane >> 2, tg = lane & 3;
    const float scale = 0.08838834764831845f;

    const float* kb = kt + ((size_t)b * Gg + gh) * SS * HD;   // [s][d]
    const float* vb = vt + ((size_t)b * Gg + gh) * (size_t)HD * SS; // [d][s]
    const uint8_t* mb = mask + ((size_t)b * Tt + qt * 128) * SS;

    auto load_stage = [&](int ti, int s) {
        const float* kbt = kb + (size_t)ti * 64 * HD;
        const float* vbt = vb + ti * 64;
        #pragma unroll
        for (int t = 0; t < 8; t++) {
            int c = tid + t * 256;
            int krow = c >> 5, kcol = (c & 31) << 2;      // K: 64 rows x 32 chunks
            unsigned dk = (unsigned)__cvta_generic_to_shared(
                &Ks[s * KSTG + krow * 136 + kcol]);
            CPASYNC16(dk, kbt + krow * HD + kcol);
            int vrow = c >> 4, vcol = (c & 15) << 2;      // V: 128 rows x 16 chunks
            unsigned dv = (unsigned)__cvta_generic_to_shared(
                &Vs[s * VSTG + vrow * 72 + vcol]);
            CPASYNC16(dv, vbt + (size_t)vrow * SS + vcol);
        }
        #pragma unroll
        for (int t = 0; t < 2; t++) {
            int c = tid + t * 256;
            int row = c >> 2, c16 = (c & 3) << 4;
            unsigned dm = (unsigned)__cvta_generic_to_shared(
                &Msk[s * 8192 + row * 64 + c16]);
            CPASYNC16(dm, mb + (size_t)row * SS + ti * 64 + c16);
        }
        asm volatile("cp.async.commit_group;\n");
    };

    // Q tile load + scale + tf32 round (once)
    const float* qb = q + (((size_t)b * Hh + h) * Tt + qt * 128) * HD;
    for (int i = tid; i < 4096; i += 256) {
        int r = i >> 5, cg = (i & 31) << 2;
        float4 v = *(const float4*)&qb[(size_t)r * HD + cg];
        uint4 u;
        u.x = f2t(v.x * scale); u.y = f2t(v.y * scale);
        u.z = f2t(v.z * scale); u.w = f2t(v.w * scale);
        *(uint4*)&Qs[r * 136 + cg] = u;
    }

    float oacc[16][4];
    #pragma unroll
    for (int nt = 0; nt < 16; nt++)
        #pragma unroll
        for (int e = 0; e < 4; e++) oacc[nt][e] = 0.0f;
    float m0r = -1e30f, m1r = -1e30f, l0 = 0.0f, l1 = 0.0f;
    int qrow = wq * 16;

    load_stage(0, 0);

    const int NT = SS / 64;
    for (int ti = 0; ti < NT; ti++) {
        if (ti + 1 < NT) {
            load_stage(ti + 1, (ti + 1) & 1);
            asm volatile("cp.async.wait_group 1;\n");
        } else {
            asm volatile("cp.async.wait_group 0;\n");
        }
        __syncthreads();

        const unsigned* Kb = Ks + (ti & 1) * KSTG;
        const unsigned* Vb = Vs + (ti & 1) * VSTG;
        const uint8_t*  Mb = Msk + (ti & 1) * 8192;

        // S = Q K^T; k-slot remap: slot tg <- d=ks+2tg, slot tg+4 <- d=ks+2tg+1
        float sacc[8][4];
        #pragma unroll
        for (int nt = 0; nt < 8; nt++)
            #pragma unroll
            for (int e = 0; e < 4; e++) sacc[nt][e] = 0.0f;

        #pragma unroll
        for (int ks = 0; ks < 128; ks += 8) {
            uint2 qlo = *(const uint2*)&Qs[(qrow + g) * 136 + ks + 2 * tg];
            uint2 qhi = *(const uint2*)&Qs[(qrow + g + 8) * 136 + ks + 2 * tg];
            #pragma unroll
            for (int nt = 0; nt < 8; nt++) {
                uint2 bb = *(const uint2*)&Kb[(nt * 8 + g) * 136 + ks + 2 * tg];
                mma8(sacc[nt], qlo.x, qhi.x, qlo.y, qhi.y, bb.x, bb.y);
            }
        }

        #pragma unroll
        for (int nt = 0; nt < 8; nt++) {
            unsigned short mm0 = *(const unsigned short*)&Mb[(qrow + g) * 64 + nt * 8 + 2 * tg];
            unsigned short mm1 = *(const unsigned short*)&Mb[(qrow + g + 8) * 64 + nt * 8 + 2 * tg];
            if (mm0 & 0x00FF) sacc[nt][0] = -1e30f;
            if (mm0 & 0xFF00) sacc[nt][1] = -1e30f;
            if (mm1 & 0x00FF) sacc[nt][2] = -1e30f;
            if (mm1 & 0xFF00) sacc[nt][3] = -1e30f;
        }

        float mx0 = -1e30f, mx1 = -1e30f;
        #pragma unroll
        for (int nt = 0; nt < 8; nt++) {
            mx0 = fmaxf(mx0, fmaxf(sacc[nt][0], sacc[nt][1]));
            mx1 = fmaxf(mx1, fmaxf(sacc[nt][2], sacc[nt][3]));
        }
        mx0 = fmaxf(mx0, __shfl_xor_sync(0xffffffffu, mx0, 1));
        mx0 = fmaxf(mx0, __shfl_xor_sync(0xffffffffu, mx0, 2));
        mx1 = fmaxf(mx1, __shfl_xor_sync(0xffffffffu, mx1, 1));
        mx1 = fmaxf(mx1, __shfl_xor_sync(0xffffffffu, mx1, 2));
        float mn0 = fmaxf(m0r, mx0), mn1 = fmaxf(m1r, mx1);
        float al0 = __expf(m0r - mn0), al1 = __expf(m1r - mn1);
        m0r = mn0; m1r = mn1;

        // P = exp(S - m); fragments are ALREADY PV A-operands (V transposed):
        // pu[kt][0] = P[g][kt*8+2tg]   -> A slot tg    (row g)
        // pu[kt][1] = P[g][kt*8+2tg+1] -> A slot tg+4  (row g)
        // pu[kt][2] = P[g+8][kt*8+2tg] -> A slot tg    (row g+8)
        // pu[kt][3] -> A slot tg+4 (row g+8)
        unsigned pu[8][4];
        float rs0 = 0.0f, rs1 = 0.0f;
        #pragma unroll
        for (int nt = 0; nt < 8; nt++) {
            float p0 = __expf(sacc[nt][0] - mn0);
            float p1 = __expf(sacc[nt][1] - mn0);
            float p2 = __expf(sacc[nt][2] - mn1);
            float p3 = __expf(sacc[nt][3] - mn1);
            rs0 += p0 + p1; rs1 += p2 + p3;
            pu[nt][0] = f2t(p0); pu[nt][1] = f2t(p1);
            pu[nt][2] = f2t(p2); pu[nt][3] = f2t(p3);
        }
        rs0 += __shfl_xor_sync(0xffffffffu, rs0, 1);
        rs0 += __shfl_xor_sync(0xffffffffu, rs0, 2);
        rs1 += __shfl_xor_sync(0xffffffffu, rs1, 1);
        rs1 += __shfl_xor_sync(0xffffffffu, rs1, 2);
        l0 = l0 * al0 + rs0;
        l1 = l1 * al1 + rs1;

        #pragma unroll
        for (int nt = 0; nt < 16; nt++) {
            oacc[nt][0] *= al0; oacc[nt][1] *= al0;
            oacc[nt][2] *= al1; oacc[nt][3] *= al1;
        }

        // PV: B slot tg <- key kt*8+2tg, slot tg+4 <- key kt*8+2tg+1 (uint2)
        #pragma unroll
        for (int kt2 = 0; kt2 < 8; kt2++) {
            unsigned a0 = pu[kt2][0], a1 = pu[kt2][2];
            unsigned a2 = pu[kt2][1], a3 = pu[kt2][3];
            #pragma unroll
            for (int nt = 0; nt < 16; nt++) {
                uint2 vv = *(const uint2*)&Vb[(nt * 8 + g) * 72 + kt2 * 8 + 2 * tg];
                mma8(oacc[nt], a0, a1, a2, a3, vv.x, vv.y);
            }
        }
        __syncthreads();
    }

    // epilogue: ctx tf32-rounded so O-projection can feed mma directly
    float il0 = 1.0f / l0, il1 = 1.0f / l1;
    int tok0 = qt * 128 + qrow + g;
    #pragma unroll
    for (int nt = 0; nt < 16; nt++) {
        int d = nt * 8 + 2 * tg;
        float2 v0 = make_float2(__uint_as_float(f2t(oacc[nt][0] * il0)),
                                __uint_as_float(f2t(oacc[nt][1] * il0)));
        float2 v1 = make_float2(__uint_as_float(f2t(oacc[nt][2] * il1)),
                                __uint_as_float(f2t(oacc[nt][3] * il1)));
        *(float2*)&ctx[(((size_t)b * Tt + tok0) * Hh + h) * HD + d] = v0;
        *(float2*)&ctx[(((size_t)b * Tt + tok0 + 8) * Hh + h) * HD + d] = v1;
    }
}

// ---------------------------------------------------------------------------
extern "C" void kernel_launch(void* const* d_in, const int* in_sizes, int n_in,
                              void* d_out, int out_size)
{
    const float*   x       = (const float*)d_in[0];
    const uint8_t* mask    = (const uint8_t*)d_in[1];
    const float*   cosT    = (const float*)d_in[2];
    const float*   sinT    = (const float*)d_in[3];
    const int*     pos     = (const int*)d_in[4];
    const float*   cache_k = (const float*)d_in[5];
    const float*   cache_v = (const float*)d_in[6];
    const float*   q_w     = (const float*)d_in[7];
    const float*   k_w     = (const float*)d_in[8];
    const float*   v_w     = (const float*)d_in[9];
    const float*   o_w     = (const float*)d_in[10];
    const float*   qn_w    = (const float*)d_in[11];
    const float*   kn_w    = (const float*)d_in[12];

    float* out_ctx = (float*)d_out;
    float* out_k   = out_ctx + (size_t)Bb * Tt * Hh * HD;
    float* out_v   = out_k   + (size_t)Bb * Gg * SS * HD;

    float *xr, *wqkv, *owr, *qkv, *qf, *ctx, *ktr, *vtr;
    cudaGetSymbolAddress((void**)&xr,   g_xr);
    cudaGetSymbolAddress((void**)&wqkv, g_wqkv);
    cudaGetSymbolAddress((void**)&owr,  g_owr);
    cudaGetSymbolAddress((void**)&qkv,  g_qkv);
    cudaGetSymbolAddress((void**)&qf,   g_q);
    cudaGetSymbolAddress((void**)&ctx,  g_ctx);
    cudaGetSymbolAddress((void**)&ktr,  g_kt);
    cudaGetSymbolAddress((void**)&vtr,  g_vt);

    // cache halves: k exact + rounded; v exact only
    {
        int n4 = Bb * Gg * CACHEN * HD / 4;
        int blocks = (n4 + 255) / 256;
        copy_cache_kernel<<<blocks, 256>>>((const float4*)cache_k, (float4*)out_k, (float4*)ktr);
        copy_cache_kernel<<<blocks, 256>>>((const float4*)cache_v, (float4*)out_v, nullptr);
    }

    // tf32 pre-rounding of GEMM operands
    {
        int n4x = 2048 * 2048 / 4;
        round_copy_kernel<<<(n4x + 255) / 256, 256>>>((const float4*)x, (float4*)xr, n4x);
        int n4o = 2048 * 2048 / 4;
        round_copy_kernel<<<(n4o + 255) / 256, 256>>>((const float4*)o_w, (float4*)owr, n4o);
        int nw = 2048 * 3072;
        pack_wqkv_kernel<<<(nw + 255) / 256, 256>>>(q_w, k_w, v_w, wqkv);
    }

    // fused QKV projection: [2048,2048] @ [2048,3072]
    size_t gsmem = (size_t)(2 * 128 * 40 + 2 * 32 * 132) * 4;
    cudaFuncSetAttribute(gemm_tf32_db, cudaFuncAttributeMaxDynamicSharedMemorySize, (int)gsmem);
    gemm_tf32_db<<<dim3(24, 16), 256, gsmem>>>(xr, wqkv, qkv, 2048, 3072, 2048);

    // RMSNorm + RoPE; K into k_full (exact) + k_tf32 scratch (rounded)
    norm_rope_kernel<<<Bb * Tt * Hh, 128>>>(qkv, 0,    qn_w, cosT, sinT, pos, qf,    nullptr, Hh, Tt, 0);
    norm_rope_kernel<<<Bb * Tt * Gg, 128>>>(qkv, 2048, kn_w, cosT, sinT, pos, out_k, ktr,     Gg, SS, CACHEN);

    // V into v_full (exact)
    {
        int n = Bb * Tt * Gg * HD;
        scatter_v_kernel<<<(n + 255) / 256, 256>>>(qkv, out_v);
    }

    // rounded TRANSPOSED V scratch [B,G,HD,S] from completed v_full
    transpose_round_kernel<<<dim3(SS / 32, HD / 32, Bb * Gg), 256>>>(out_v, vtr);

    // attention (tf32 tensor cores, cp.async double-buffered, shuffle-free PV)
    size_t smem = (size_t)(128 * 136 + 2 * 64 * 136 + 2 * 128 * 72) * 4 + 2 * 128 * 64;
    cudaFuncSetAttribute(attn_tf32, cudaFuncAttributeMaxDynamicSharedMemorySize, (int)smem);
    attn_tf32<<<dim3(Tt / 128, Hh, Bb), 256, smem>>>(qf, ktr, vtr, mask, ctx);

    // output projection
    gemm_tf32_db<<<dim3(16, 16), 256, gsmem>>>(ctx, owr, out_ctx, 2048, 2048, 2048);
}

// round 7
// speedup vs baseline: 6.4209x; 1.0029x over previous
#include <cuda_runtime.h>
#include <stdint.h>

#define Bb 4
#define Tt 512
#define Hh 16
#define Gg 4
#define HD 128
#define CACHEN 3584
#define SS 4096

// Scratch (static device arrays; no allocation allowed)
__device__ float g_xr   [2048*2048];     // tf32-rounded x
__device__ float g_wqkv [2048*3072];     // tf32-rounded [q_w | k_w | v_w]
__device__ float g_owr  [2048*2048];     // tf32-rounded o_w
__device__ float g_qkv  [2048*3072];     // fused projection output [B*T, 3072]
__device__ float g_q    [Bb*Hh*Tt*HD];   // [B,H,T,HD]
__device__ float g_ctx  [Bb*Tt*Hh*HD];   // [B,T,H,HD] (tf32-rounded)
__device__ float g_kt   [Bb*Gg*SS*HD];   // tf32-rounded k_full [B,G,S,HD]
__device__ float g_vt   [Bb*Gg*HD*SS];   // tf32-rounded v_full TRANSPOSED [B,G,HD,S]

// Side-stream resources, created once at program load (before any capture).
struct GpuRes {
    cudaStream_t s2;
    cudaEvent_t e0, e2;
    GpuRes() {
        cudaStreamCreateWithFlags(&s2, cudaStreamNonBlocking);
        cudaEventCreateWithFlags(&e0, cudaEventDisableTiming);
        cudaEventCreateWithFlags(&e2, cudaEventDisableTiming);
    }
};
static GpuRes g_res;

__device__ __forceinline__ unsigned f2t(float x) {
    unsigned r;
    asm("cvt.rna.tf32.f32 %0, %1;" : "=r"(r) : "f"(x));
    return r;
}

__device__ __forceinline__ void mma8(float* c,
    unsigned a0, unsigned a1, unsigned a2, unsigned a3,
    unsigned b0, unsigned b1)
{
    asm volatile(
        "mma.sync.aligned.m16n8k8.row.col.f32.tf32.tf32.f32 "
        "{%0,%1,%2,%3}, {%4,%5,%6,%7}, {%8,%9}, {%0,%1,%2,%3};"
        : "+f"(c[0]), "+f"(c[1]), "+f"(c[2]), "+f"(c[3])
        : "r"(a0), "r"(a1), "r"(a2), "r"(a3), "r"(b0), "r"(b1));
}

#define CPASYNC16(dst_sm, src_gm) \
    asm volatile("cp.async.cg.shared.global [%0], [%1], 16;\n" \
                 :: "r"(dst_sm), "l"(src_gm))

// ---------------------------------------------------------------------------
// Prep kernels
// ---------------------------------------------------------------------------
__global__ __launch_bounds__(256) void round_copy_kernel(
    const float4* __restrict__ src, float4* __restrict__ dst, int n4)
{
    int i = blockIdx.x * blockDim.x + threadIdx.x;
    if (i >= n4) return;
    float4 v = src[i];
    float4 o;
    o.x = __uint_as_float(f2t(v.x)); o.y = __uint_as_float(f2t(v.y));
    o.z = __uint_as_float(f2t(v.z)); o.w = __uint_as_float(f2t(v.w));
    dst[i] = o;
}

__global__ __launch_bounds__(256) void pack_wqkv_kernel(
    const float* __restrict__ qw, const float* __restrict__ kw,
    const float* __restrict__ vw, float* __restrict__ dst)
{
    int i = blockIdx.x * blockDim.x + threadIdx.x;
    if (i >= 2048 * 3072) return;
    int k = i / 3072, c = i % 3072;
    float v;
    if (c < 2048)      v = qw[(size_t)k * 2048 + c];
    else if (c < 2560) v = kw[(size_t)k * 512 + (c - 2048)];
    else               v = vw[(size_t)k * 512 + (c - 2560)];
    dst[i] = __uint_as_float(f2t(v));
}

// Tiled transpose + tf32 round into [bg][d][s], reading sources directly:
// s < CACHE from cache_v, s >= CACHE from the fused qkv buffer.
// Tiles never straddle s=CACHE (3584 = 112*32).
__global__ __launch_bounds__(256) void transpose_round_kernel(
    const float* __restrict__ cache_v, const float* __restrict__ qkv,
    float* __restrict__ dst)
{
    __shared__ float tile[32][33];
    int bg = blockIdx.z;
    int b = bg >> 2, g = bg & 3;
    int s0 = blockIdx.x << 5, d0 = blockIdx.y << 5;
    int tx = threadIdx.x & 31, ty = threadIdx.x >> 5;   // 32 x 8

    if (s0 < CACHEN) {
        const float* s = cache_v + (size_t)bg * CACHEN * HD;
        #pragma unroll
        for (int r = 0; r < 32; r += 8)
            tile[ty + r][tx] = s[(size_t)(s0 + ty + r) * HD + d0 + tx];
    } else {
        #pragma unroll
        for (int r = 0; r < 32; r += 8) {
            int t = s0 + ty + r - CACHEN;
            tile[ty + r][tx] =
                qkv[(size_t)(b * Tt + t) * 3072 + 2560 + g * HD + d0 + tx];
        }
    }
    __syncthreads();
    float* d = dst + (size_t)bg * HD * SS;
    #pragma unroll
    for (int r = 0; r < 32; r += 8)
        d[(size_t)(d0 + ty + r) * SS + s0 + tx] =
            __uint_as_float(f2t(tile[tx][ty + r]));
}

// ---------------------------------------------------------------------------
// tf32 GEMM, cp.async 3-stage pipelined, uint2 A-fragments (slot-remapped).
// C[M,N] = A[M,K] @ B[K,N]. Block 128x128, BK=32, 256 thr, 2 CTA/SM.
// ---------------------------------------------------------------------------
__global__ __launch_bounds__(256, 2) void gemm_tf32_db(
    const float* __restrict__ A, const float* __restrict__ Bm,
    float* __restrict__ C, int M, int N, int K)
{
    extern __shared__ unsigned sm[];
    unsigned* As = sm;                    // 3 stages of [128][40]
    unsigned* Bs = sm + 3 * 128 * 40;     // 3 stages of [32][132]
    const int ASTG = 128 * 40, BSTG = 32 * 132;

    int tid = threadIdx.x, lane = tid & 31, warp = tid >> 5;
    int g = lane >> 2, tg = lane & 3;
    int m0 = blockIdx.y << 7, n0 = blockIdx.x << 7;
    int wm = (warp >> 2) << 6, wn = (warp & 3) << 5;

    float acc[4][4][4];
    #pragma unroll
    for (int i = 0; i < 4; i++)
        #pragma unroll
        for (int j = 0; j < 4; j++)
            #pragma unroll
            for (int e = 0; e < 4; e++) acc[i][j][e] = 0.0f;

    int ar[4], ac[4], br[4], bc[4];
    #pragma unroll
    for (int t = 0; t < 4; t++) {
        int i = tid + t * 256;
        ar[t] = i >> 3;  ac[t] = (i & 7) << 2;
        br[t] = i >> 5;  bc[t] = (i & 31) << 2;
    }

    auto load_stage = [&](int k0, int s) {
        #pragma unroll
        for (int t = 0; t < 4; t++) {
            unsigned da = (unsigned)__cvta_generic_to_shared(
                &As[s * ASTG + ar[t] * 40 + ac[t]]);
            CPASYNC16(da, &A[(size_t)(m0 + ar[t]) * K + k0 + ac[t]]);
            unsigned db = (unsigned)__cvta_generic_to_shared(
                &Bs[s * BSTG + br[t] * 132 + bc[t]]);
            CPASYNC16(db, &Bm[(size_t)(k0 + br[t]) * N + n0 + bc[t]]);
        }
        asm volatile("cp.async.commit_group;\n");
    };

    int niter = K >> 5;
    load_stage(0, 0);
    load_stage(32, 1);

    int sc = 0;        // stage being computed
    int sl = 2;        // stage to load into next
    for (int it = 0; it < niter; it++) {
        if (it + 2 < niter) {
            load_stage((it + 2) << 5, sl);
            sl = (sl + 1 == 3) ? 0 : sl + 1;
            asm volatile("cp.async.wait_group 2;\n");
        } else if (it + 1 < niter) {
            asm volatile("cp.async.wait_group 1;\n");
        } else {
            asm volatile("cp.async.wait_group 0;\n");
        }
        __syncthreads();

        const unsigned* Ab = As + sc * ASTG;
        const unsigned* Bbuf = Bs + sc * BSTG;
        sc = (sc + 1 == 3) ? 0 : sc + 1;
        #pragma unroll
        for (int ks = 0; ks < 32; ks += 8) {
            // slot remap: k-slot tg <- col ks+2tg, slot tg+4 <- col ks+2tg+1
            uint2 alo[4], ahi[4];
            #pragma unroll
            for (int mt = 0; mt < 4; mt++) {
                int r = wm + mt * 16;
                alo[mt] = *(const uint2*)&Ab[(r + g) * 40 + ks + 2 * tg];
                ahi[mt] = *(const uint2*)&Ab[(r + g + 8) * 40 + ks + 2 * tg];
            }
            #pragma unroll
            for (int nt = 0; nt < 4; nt++) {
                unsigned b0 = Bbuf[(ks + 2 * tg) * 132 + wn + nt * 8 + g];
                unsigned b1 = Bbuf[(ks + 2 * tg + 1) * 132 + wn + nt * 8 + g];
                #pragma unroll
                for (int mt = 0; mt < 4; mt++)
                    mma8(acc[mt][nt], alo[mt].x, ahi[mt].x, alo[mt].y, ahi[mt].y, b0, b1);
            }
        }
        __syncthreads();
    }

    #pragma unroll
    for (int mt = 0; mt < 4; mt++)
        #pragma unroll
        for (int nt = 0; nt < 4; nt++) {
            int r0 = m0 + wm + mt * 16 + g;
            int c  = n0 + wn + nt * 8 + 2 * tg;
            float2 v0 = make_float2(acc[mt][nt][0], acc[mt][nt][1]);
            float2 v1 = make_float2(acc[mt][nt][2], acc[mt][nt][3]);
            *(float2*)&C[(size_t)r0 * N + c] = v0;
            *(float2*)&C[(size_t)(r0 + 8) * N + c] = v1;
        }
}

// ---------------------------------------------------------------------------
// Fused per-head RMSNorm + RoPE; optional tf32-rounded second output.
// ---------------------------------------------------------------------------
__global__ __launch_bounds__(128) void norm_rope_kernel(
    const float* __restrict__ raw, int coloff, const float* __restrict__ nw,
    const float* __restrict__ cosT, const float* __restrict__ sinT,
    const int* __restrict__ pos, float* __restrict__ out,
    float* __restrict__ outr, int NH, int Tout, int toff)
{
    int idx = blockIdx.x;          // (b*T + t)*NH + h
    int h  = idx % NH;
    int bt = idx / NH;
    int t  = bt % Tt;
    int b  = bt / Tt;
    int d  = threadIdx.x;

    __shared__ float zn[128];
    __shared__ float red[4];

    float z = raw[(size_t)bt * 3072 + coloff + h * HD + d];
    float ss = z * z;
    #pragma unroll
    for (int o = 16; o; o >>= 1) ss += __shfl_xor_sync(0xffffffffu, ss, o);
    if ((d & 31) == 0) red[d >> 5] = ss;
    __syncthreads();
    float tot = red[0] + red[1] + red[2] + red[3];
    float r = rsqrtf(tot * (1.0f / 128.0f) + 1e-6f);
    float v = z * r * nw[d];
    zn[d] = v;
    __syncthreads();

    int p = pos[bt];
    float c = cosT[p * HD + d];
    float s = sinT[p * HD + d];
    float rot = (d < 64) ? -zn[d + 64] : zn[d - 64];
    float o = fmaf(v, c, rot * s);
    size_t oi = (((size_t)b * NH + h) * Tout + (toff + t)) * HD + d;
    out[oi] = o;
    if (outr) outr[oi] = __uint_as_float(f2t(o));
}

// V scatter: exact into v_full only
__global__ __launch_bounds__(256) void scatter_v_kernel(
    const float* __restrict__ qkv, float* __restrict__ vf)
{
    int i = blockIdx.x * blockDim.x + threadIdx.x;
    const int n = Bb * Tt * Gg * HD;
    if (i >= n) return;
    int d = i & 127;
    int g = (i >> 7) & 3;
    int t = (i >> 9) % Tt;
    int b = i / (HD * Gg * Tt);
    int bt = b * Tt + t;
    vf[(((size_t)(b * Gg + g)) * SS + CACHEN + t) * HD + d] =
        qkv[(size_t)bt * 3072 + 2560 + g * HD + d];
}

// Cache copy: exact + optional rounded
__global__ __launch_bounds__(256) void copy_cache_kernel(
    const float4* __restrict__ src, float4* __restrict__ dst,
    float4* __restrict__ dstr)
{
    int i = blockIdx.x * blockDim.x + threadIdx.x;
    const int per = CACHEN * HD / 4;
    const int n4  = Bb * Gg * per;
    if (i >= n4) return;
    int bg = i / per, r = i % per;
    size_t oi = (size_t)bg * (SS * HD / 4) + r;
    float4 v = src[i];
    dst[oi] = v;
    if (dstr) {
        float4 o;
        o.x = __uint_as_float(f2t(v.x)); o.y = __uint_as_float(f2t(v.y));
        o.z = __uint_as_float(f2t(v.z)); o.w = __uint_as_float(f2t(v.w));
        dstr[oi] = o;
    }
}

// ---------------------------------------------------------------------------
// tf32 flash attention, cp.async double-buffered, shuffle-free PV phase.
// (unchanged from round 6)
// ---------------------------------------------------------------------------
__global__ __launch_bounds__(256) void attn_tf32(
    const float* __restrict__ q, const float* __restrict__ kt,
    const float* __restrict__ vt, const uint8_t* __restrict__ mask,
    float* __restrict__ ctx)
{
    extern __shared__ char smraw[];
    unsigned* Qs = (unsigned*)smraw;               // [128][136]
    unsigned* Ks = Qs + 128 * 136;                 // 2 x [64 key][136]
    unsigned* Vs = Ks + 2 * 64 * 136;              // 2 x [128 d][72]
    uint8_t*  Msk = (uint8_t*)(Vs + 2 * 128 * 72); // 2 x [128][64]
    const int KSTG = 64 * 136, VSTG = 128 * 72;

    int qt = blockIdx.x, h = blockIdx.y, b = blockIdx.z;
    int gh = h >> 2;
    int tid = threadIdx.x, lane = tid & 31, wq = tid >> 5;
    int g = lane >> 2, tg = lane & 3;
    const float scale = 0.08838834764831845f;

    const float* kb = kt + ((size_t)b * Gg + gh) * SS * HD;
    const float* vb = vt + ((size_t)b * Gg + gh) * (size_t)HD * SS;
    const uint8_t* mb = mask + ((size_t)b * Tt + qt * 128) * SS;

    auto load_stage = [&](int ti, int s) {
        const float* kbt = kb + (size_t)ti * 64 * HD;
        const float* vbt = vb + ti * 64;
        #pragma unroll
        for (int t = 0; t < 8; t++) {
            int c = tid + t * 256;
            int krow = c >> 5, kcol = (c & 31) << 2;
            unsigned dk = (unsigned)__cvta_generic_to_shared(
                &Ks[s * KSTG + krow * 136 + kcol]);
            CPASYNC16(dk, kbt + krow * HD + kcol);
            int vrow = c >> 4, vcol = (c & 15) << 2;
            unsigned dv = (unsigned)__cvta_generic_to_shared(
                &Vs[s * VSTG + vrow * 72 + vcol]);
            CPASYNC16(dv, vbt + (size_t)vrow * SS + vcol);
        }
        #pragma unroll
        for (int t = 0; t < 2; t++) {
            int c = tid + t * 256;
            int row = c >> 2, c16 = (c & 3) << 4;
            unsigned dm = (unsigned)__cvta_generic_to_shared(
                &Msk[s * 8192 + row * 64 + c16]);
            CPASYNC16(dm, mb + (size_t)row * SS + ti * 64 + c16);
        }
        asm volatile("cp.async.commit_group;\n");
    };

    const float* qb = q + (((size_t)b * Hh + h) * Tt + qt * 128) * HD;
    for (int i = tid; i < 4096; i += 256) {
        int r = i >> 5, cg = (i & 31) << 2;
        float4 v = *(const float4*)&qb[(size_t)r * HD + cg];
        uint4 u;
        u.x = f2t(v.x * scale); u.y = f2t(v.y * scale);
        u.z = f2t(v.z * scale); u.w = f2t(v.w * scale);
        *(uint4*)&Qs[r * 136 + cg] = u;
    }

    float oacc[16][4];
    #pragma unroll
    for (int nt = 0; nt < 16; nt++)
        #pragma unroll
        for (int e = 0; e < 4; e++) oacc[nt][e] = 0.0f;
    float m0r = -1e30f, m1r = -1e30f, l0 = 0.0f, l1 = 0.0f;
    int qrow = wq * 16;

    load_stage(0, 0);

    const int NT = SS / 64;
    for (int ti = 0; ti < NT; ti++) {
        if (ti + 1 < NT) {
            load_stage(ti + 1, (ti + 1) & 1);
            asm volatile("cp.async.wait_group 1;\n");
        } else {
            asm volatile("cp.async.wait_group 0;\n");
        }
        __syncthreads();

        const unsigned* Kb = Ks + (ti & 1) * KSTG;
        const unsigned* Vb = Vs + (ti & 1) * VSTG;
        const uint8_t*  Mb = Msk + (ti & 1) * 8192;

        float sacc[8][4];
        #pragma unroll
        for (int nt = 0; nt < 8; nt++)
            #pragma unroll
            for (int e = 0; e < 4; e++) sacc[nt][e] = 0.0f;

        #pragma unroll
        for (int ks = 0; ks < 128; ks += 8) {
            uint2 qlo = *(const uint2*)&Qs[(qrow + g) * 136 + ks + 2 * tg];
            uint2 qhi = *(const uint2*)&Qs[(qrow + g + 8) * 136 + ks + 2 * tg];
            #pragma unroll
            for (int nt = 0; nt < 8; nt++) {
                uint2 bb = *(const uint2*)&Kb[(nt * 8 + g) * 136 + ks + 2 * tg];
                mma8(sacc[nt], qlo.x, qhi.x, qlo.y, qhi.y, bb.x, bb.y);
            }
        }

        #pragma unroll
        for (int nt = 0; nt < 8; nt++) {
            unsigned short mm0 = *(const unsigned short*)&Mb[(qrow + g) * 64 + nt * 8 + 2 * tg];
            unsigned short mm1 = *(const unsigned short*)&Mb[(qrow + g + 8) * 64 + nt * 8 + 2 * tg];
            if (mm0 & 0x00FF) sacc[nt][0] = -1e30f;
            if (mm0 & 0xFF00) sacc[nt][1] = -1e30f;
            if (mm1 & 0x00FF) sacc[nt][2] = -1e30f;
            if (mm1 & 0xFF00) sacc[nt][3] = -1e30f;
        }

        float mx0 = -1e30f, mx1 = -1e30f;
        #pragma unroll
        for (int nt = 0; nt < 8; nt++) {
            mx0 = fmaxf(mx0, fmaxf(sacc[nt][0], sacc[nt][1]));
            mx1 = fmaxf(mx1, fmaxf(sacc[nt][2], sacc[nt][3]));
        }
        mx0 = fmaxf(mx0, __shfl_xor_sync(0xffffffffu, mx0, 1));
        mx0 = fmaxf(mx0, __shfl_xor_sync(0xffffffffu, mx0, 2));
        mx1 = fmaxf(mx1, __shfl_xor_sync(0xffffffffu, mx1, 1));
        mx1 = fmaxf(mx1, __shfl_xor_sync(0xffffffffu, mx1, 2));
        float mn0 = fmaxf(m0r, mx0), mn1 = fmaxf(m1r, mx1);
        float al0 = __expf(m0r - mn0), al1 = __expf(m1r - mn1);
        m0r = mn0; m1r = mn1;

        unsigned pu[8][4];
        float rs0 = 0.0f, rs1 = 0.0f;
        #pragma unroll
        for (int nt = 0; nt < 8; nt++) {
            float p0 = __expf(sacc[nt][0] - mn0);
            float p1 = __expf(sacc[nt][1] - mn0);
            float p2 = __expf(sacc[nt][2] - mn1);
            float p3 = __expf(sacc[nt][3] - mn1);
            rs0 += p0 + p1; rs1 += p2 + p3;
            pu[nt][0] = f2t(p0); pu[nt][1] = f2t(p1);
            pu[nt][2] = f2t(p2); pu[nt][3] = f2t(p3);
        }
        rs0 += __shfl_xor_sync(0xffffffffu, rs0, 1);
        rs0 += __shfl_xor_sync(0xffffffffu, rs0, 2);
        rs1 += __shfl_xor_sync(0xffffffffu, rs1, 1);
        rs1 += __shfl_xor_sync(0xffffffffu, rs1, 2);
        l0 = l0 * al0 + rs0;
        l1 = l1 * al1 + rs1;

        #pragma unroll
        for (int nt = 0; nt < 16; nt++) {
            oacc[nt][0] *= al0; oacc[nt][1] *= al0;
            oacc[nt][2] *= al1; oacc[nt][3] *= al1;
        }

        #pragma unroll
        for (int kt2 = 0; kt2 < 8; kt2++) {
            unsigned a0 = pu[kt2][0], a1 = pu[kt2][2];
            unsigned a2 = pu[kt2][1], a3 = pu[kt2][3];
            #pragma unroll
            for (int nt = 0; nt < 16; nt++) {
                uint2 vv = *(const uint2*)&Vb[(nt * 8 + g) * 72 + kt2 * 8 + 2 * tg];
                mma8(oacc[nt], a0, a1, a2, a3, vv.x, vv.y);
            }
        }
        __syncthreads();
    }

    float il0 = 1.0f / l0, il1 = 1.0f / l1;
    int tok0 = qt * 128 + qrow + g;
    #pragma unroll
    for (int nt = 0; nt < 16; nt++) {
        int d = nt * 8 + 2 * tg;
        float2 v0 = make_float2(__uint_as_float(f2t(oacc[nt][0] * il0)),
                                __uint_as_float(f2t(oacc[nt][1] * il0)));
        float2 v1 = make_float2(__uint_as_float(f2t(oacc[nt][2] * il1)),
                                __uint_as_float(f2t(oacc[nt][3] * il1)));
        *(float2*)&ctx[(((size_t)b * Tt + tok0) * Hh + h) * HD + d] = v0;
        *(float2*)&ctx[(((size_t)b * Tt + tok0 + 8) * Hh + h) * HD + d] = v1;
    }
}

// ---------------------------------------------------------------------------
extern "C" void kernel_launch(void* const* d_in, const int* in_sizes, int n_in,
                              void* d_out, int out_size)
{
    const float*   x       = (const float*)d_in[0];
    const uint8_t* mask    = (const uint8_t*)d_in[1];
    const float*   cosT    = (const float*)d_in[2];
    const float*   sinT    = (const float*)d_in[3];
    const int*     pos     = (const int*)d_in[4];
    const float*   cache_k = (const float*)d_in[5];
    const float*   cache_v = (const float*)d_in[6];
    const float*   q_w     = (const float*)d_in[7];
    const float*   k_w     = (const float*)d_in[8];
    const float*   v_w     = (const float*)d_in[9];
    const float*   o_w     = (const float*)d_in[10];
    const float*   qn_w    = (const float*)d_in[11];
    const float*   kn_w    = (const float*)d_in[12];

    float* out_ctx = (float*)d_out;
    float* out_k   = out_ctx + (size_t)Bb * Tt * Hh * HD;
    float* out_v   = out_k   + (size_t)Bb * Gg * SS * HD;

    float *xr, *wqkv, *owr, *qkv, *qf, *ctx, *ktr, *vtr;
    cudaGetSymbolAddress((void**)&xr,   g_xr);
    cudaGetSymbolAddress((void**)&wqkv, g_wqkv);
    cudaGetSymbolAddress((void**)&owr,  g_owr);
    cudaGetSymbolAddress((void**)&qkv,  g_qkv);
    cudaGetSymbolAddress((void**)&qf,   g_q);
    cudaGetSymbolAddress((void**)&ctx,  g_ctx);
    cudaGetSymbolAddress((void**)&ktr,  g_kt);
    cudaGetSymbolAddress((void**)&vtr,  g_vt);

    // Fork side stream for the independent copy/round work.
    cudaEventRecord(g_res.e0, 0);
    cudaStreamWaitEvent(g_res.s2, g_res.e0, 0);
    {
        int n4 = Bb * Gg * CACHEN * HD / 4;
        int blocks = (n4 + 255) / 256;
        copy_cache_kernel<<<blocks, 256, 0, g_res.s2>>>(
            (const float4*)cache_k, (float4*)out_k, (float4*)ktr);
        copy_cache_kernel<<<blocks, 256, 0, g_res.s2>>>(
            (const float4*)cache_v, (float4*)out_v, nullptr);
        int n4o = 2048 * 2048 / 4;
        round_copy_kernel<<<(n4o + 255) / 256, 256, 0, g_res.s2>>>(
            (const float4*)o_w, (float4*)owr, n4o);
    }
    cudaEventRecord(g_res.e2, g_res.s2);

    // Main stream: projection chain.
    {
        int n4x = 2048 * 2048 / 4;
        round_copy_kernel<<<(n4x + 255) / 256, 256>>>((const float4*)x, (float4*)xr, n4x);
        int nw = 2048 * 3072;
        pack_wqkv_kernel<<<(nw + 255) / 256, 256>>>(q_w, k_w, v_w, wqkv);
    }

    size_t gsmem = (size_t)(3 * 128 * 40 + 3 * 32 * 132) * 4;
    cudaFuncSetAttribute(gemm_tf32_db, cudaFuncAttributeMaxDynamicSharedMemorySize, (int)gsmem);
    gemm_tf32_db<<<dim3(24, 16), 256, gsmem>>>(xr, wqkv, qkv, 2048, 3072, 2048);

    // rounded TRANSPOSED V scratch straight from sources (needs qkv only)
    transpose_round_kernel<<<dim3(SS / 32, HD / 32, Bb * Gg), 256>>>(cache_v, qkv, vtr);

    // RMSNorm + RoPE; K into k_full (exact) + k_tf32 scratch (rounded)
    norm_rope_kernel<<<Bb * Tt * Hh, 128>>>(qkv, 0,    qn_w, cosT, sinT, pos, qf,    nullptr, Hh, Tt, 0);
    norm_rope_kernel<<<Bb * Tt * Gg, 128>>>(qkv, 2048, kn_w, cosT, sinT, pos, out_k, ktr,     Gg, SS, CACHEN);

    // V into v_full (exact)
    {
        int n = Bb * Tt * Gg * HD;
        scatter_v_kernel<<<(n + 255) / 256, 256>>>(qkv, out_v);
    }

    // Join: attention needs ktr's cache half; O-GEMM needs owr.
    cudaStreamWaitEvent(0, g_res.e2, 0);

    size_t smem = (size_t)(128 * 136 + 2 * 64 * 136 + 2 * 128 * 72) * 4 + 2 * 128 * 64;
    cudaFuncSetAttribute(attn_tf32, cudaFuncAttributeMaxDynamicSharedMemorySize, (int)smem);
    attn_tf32<<<dim3(Tt / 128, Hh, Bb), 256, smem>>>(qf, ktr, vtr, mask, ctx);

    // output projection
    gemm_tf32_db<<<dim3(16, 16), 256, gsmem>>>(ctx, owr, out_ctx, 2048, 2048, 2048);
}

// round 9
// speedup vs baseline: 11.2804x; 1.7568x over previous
#include <cuda_runtime.h>
#include <cuda_fp16.h>
#include <stdint.h>

#define Bb 4
#define Tt 512
#define Hh 16
#define Gg 4
#define HD 128
#define CACHEN 3584
#define SS 4096

// Scratch (static device arrays; no allocation allowed)
__device__ __half g_xh   [2048*2048];    // fp16 x               [M,K] K-major
__device__ __half g_wqkvh[3072*2048];    // fp16 qkv weights     [N,K] K-major
__device__ __half g_owh  [2048*2048];    // fp16 o_w             [N,K] K-major
__device__ float  g_qkv  [2048*3072];    // fused projection output (fp32)
__device__ __half g_qh   [Bb*Hh*Tt*HD];  // fp16 Q (pre-scaled) [B,H,T,HD]
__device__ __half g_ctxh [Bb*Tt*Hh*HD];  // fp16 ctx [B,T,H*HD]
__device__ __half g_kh   [Bb*Gg*SS*HD];  // fp16 k_full [B,G,S,HD]
__device__ __half g_vh   [Bb*Gg*HD*SS];  // fp16 v_full transposed [B,G,HD,S], keys permuted in 16-groups

// Side-stream resources, created once at program load (before any capture).
struct GpuRes {
    cudaStream_t s2;
    cudaEvent_t e0, e2;
    GpuRes() {
        cudaStreamCreateWithFlags(&s2, cudaStreamNonBlocking);
        cudaEventCreateWithFlags(&e0, cudaEventDisableTiming);
        cudaEventCreateWithFlags(&e2, cudaEventDisableTiming);
    }
};
static GpuRes g_res;

// pack two floats into half2 (lo, hi)
__device__ __forceinline__ unsigned ph2(float lo, float hi) {
    unsigned r;
    asm("cvt.rn.f16x2.f32 %0, %1, %2;" : "=r"(r) : "f"(hi), "f"(lo));
    return r;
}

__device__ __forceinline__ void mma16(float* c,
    unsigned a0, unsigned a1, unsigned a2, unsigned a3,
    unsigned b0, unsigned b1)
{
    asm volatile(
        "mma.sync.aligned.m16n8k16.row.col.f32.f16.f16.f32 "
        "{%0,%1,%2,%3}, {%4,%5,%6,%7}, {%8,%9}, {%0,%1,%2,%3};"
        : "+f"(c[0]), "+f"(c[1]), "+f"(c[2]), "+f"(c[3])
        : "r"(a0), "r"(a1), "r"(a2), "r"(a3), "r"(b0), "r"(b1));
}

#define CPASYNC16(dst_sm, src_gm) \
    asm volatile("cp.async.cg.shared.global [%0], [%1], 16;\n" \
                 :: "r"(dst_sm), "l"(src_gm))

// key permutation within a 16-group so PV B-fragments are contiguous uint2:
// storage position of key s: slots (2tg,2tg+1,2tg+8,2tg+9) -> halves 4tg..4tg+3
__device__ __forceinline__ int perm16(int s) {
    return ((s >> 1) & 3) * 4 + ((s >> 3) & 1) * 2 + (s & 1);
}

// ---------------------------------------------------------------------------
// Prep kernels
// ---------------------------------------------------------------------------
__global__ __launch_bounds__(256) void conv_x_kernel(
    const float4* __restrict__ src, uint2* __restrict__ dst, int n4)
{
    int i = blockIdx.x * blockDim.x + threadIdx.x;
    if (i >= n4) return;
    float4 v = src[i];
    dst[i] = make_uint2(ph2(v.x, v.y), ph2(v.z, v.w));
}

// Transposed qkv weight pack: dst[n][k] = fp16(w[k][n]) for n in [0,3072)
__global__ __launch_bounds__(256) void pack_wqkvT_kernel(
    const float* __restrict__ qw, const float* __restrict__ kw,
    const float* __restrict__ vw, __half* __restrict__ dst)
{
    __shared__ float tile[32][33];
    int k0 = blockIdx.x << 5;   // K = 2048
    int n0 = blockIdx.y << 5;   // N = 3072
    int tx = threadIdx.x & 31, ty = threadIdx.x >> 5;
    const float* src; int ncol, nbase;
    if (n0 < 2048)      { src = qw; ncol = 2048; nbase = 0; }
    else if (n0 < 2560) { src = kw; ncol = 512;  nbase = 2048; }
    else                { src = vw; ncol = 512;  nbase = 2560; }
    #pragma unroll
    for (int r = 0; r < 32; r += 8)
        tile[ty + r][tx] = src[(size_t)(k0 + ty + r) * ncol + (n0 - nbase) + tx];
    __syncthreads();
    #pragma unroll
    for (int r = 0; r < 32; r += 8)
        dst[(size_t)(n0 + ty + r) * 2048 + k0 + tx] =
            __float2half_rn(tile[tx][ty + r]);
}

// o_w transpose: dst[n][k] = fp16(src[k][n]), 2048x2048
__global__ __launch_bounds__(256) void transpose_ow_kernel(
    const float* __restrict__ src, __half* __restrict__ dst)
{
    __shared__ float tile[32][33];
    int k0 = blockIdx.x << 5, n0 = blockIdx.y << 5;
    int tx = threadIdx.x & 31, ty = threadIdx.x >> 5;
    #pragma unroll
    for (int r = 0; r < 32; r += 8)
        tile[ty + r][tx] = src[(size_t)(k0 + ty + r) * 2048 + n0 + tx];
    __syncthreads();
    #pragma unroll
    for (int r = 0; r < 32; r += 8)
        dst[(size_t)(n0 + ty + r) * 2048 + k0 + tx] =
            __float2half_rn(tile[tx][ty + r]);
}

// V: transpose + fp16 + key permutation into [bg][d][s'], sources direct.
__global__ __launch_bounds__(256) void transpose_v_kernel(
    const float* __restrict__ cache_v, const float* __restrict__ qkv,
    __half* __restrict__ dst)
{
    __shared__ float tile[32][33];
    int bg = blockIdx.z;
    int b = bg >> 2, g = bg & 3;
    int s0 = blockIdx.x << 5, d0 = blockIdx.y << 5;
    int tx = threadIdx.x & 31, ty = threadIdx.x >> 5;

    if (s0 < CACHEN) {
        const float* s = cache_v + (size_t)bg * CACHEN * HD;
        #pragma unroll
        for (int r = 0; r < 32; r += 8)
            tile[ty + r][tx] = s[(size_t)(s0 + ty + r) * HD + d0 + tx];
    } else {
        #pragma unroll
        for (int r = 0; r < 32; r += 8) {
            int t = s0 + ty + r - CACHEN;
            tile[ty + r][tx] =
                qkv[(size_t)(b * Tt + t) * 3072 + 2560 + g * HD + d0 + tx];
        }
    }
    __syncthreads();
    __half* d = dst + (size_t)bg * HD * SS;
    int sp = s0 + (tx & ~15) + perm16(tx & 15);
    #pragma unroll
    for (int r = 0; r < 32; r += 8)
        d[(size_t)(d0 + ty + r) * SS + sp] = __float2half_rn(tile[tx][ty + r]);
}

// ---------------------------------------------------------------------------
// fp16 GEMM: C[M,N] = A[M,K] @ B[N,K]^T, fp32 accumulate/output.
// Block 128x128, BK=64 halves, 256 thr, 2 CTA/SM, cp.async double-buffered.
// Fragments: k-slots {2tg,2tg+1,2tg+8,2tg+9} <- physical halves 4tg..4tg+3.
// Strides 40 words (== 8 mod 32) => conflict-free LDS.64.
// ---------------------------------------------------------------------------
__global__ __launch_bounds__(256, 2) void gemm_h(
    const __half* __restrict__ A, const __half* __restrict__ Bm,
    float* __restrict__ C, int M, int N, int K)
{
    extern __shared__ unsigned sm[];
    unsigned* As = sm;                 // 2 stages of [128][40] words
    unsigned* Bs = sm + 2 * 128 * 40;  // 2 stages of [128][40] words
    const int STG = 128 * 40;

    int tid = threadIdx.x, lane = tid & 31, warp = tid >> 5;
    int g = lane >> 2, tg = lane & 3;
    int m0 = blockIdx.y << 7, n0 = blockIdx.x << 7;
    int wm = (warp >> 2) << 6, wn = (warp & 3) << 5;

    float acc[4][4][4];
    #pragma unroll
    for (int i = 0; i < 4; i++)
        #pragma unroll
        for (int j = 0; j < 4; j++)
            #pragma unroll
            for (int e = 0; e < 4; e++) acc[i][j][e] = 0.0f;

    auto load_stage = [&](int it) {
        int s = it & 1;
        int k0 = it << 6;
        #pragma unroll
        for (int t = 0; t < 4; t++) {
            int c = tid + (t << 8);
            int row = c >> 3, ch = c & 7;       // 8 chunks of 8 halves per row
            unsigned da = (unsigned)__cvta_generic_to_shared(
                &As[s * STG + row * 40 + ch * 4]);
            CPASYNC16(da, A + (size_t)(m0 + row) * K + k0 + ch * 8);
            unsigned db = (unsigned)__cvta_generic_to_shared(
                &Bs[s * STG + row * 40 + ch * 4]);
            CPASYNC16(db, Bm + (size_t)(n0 + row) * K + k0 + ch * 8);
        }
        asm volatile("cp.async.commit_group;\n");
    };

    int niter = K >> 6;
    load_stage(0);

    for (int it = 0; it < niter; it++) {
        if (it + 1 < niter) {
            load_stage(it + 1);
            asm volatile("cp.async.wait_group 1;\n");
        } else {
            asm volatile("cp.async.wait_group 0;\n");
        }
        __syncthreads();

        const unsigned* Ab = As + (it & 1) * STG;
        const unsigned* Bbuf = Bs + (it & 1) * STG;
        #pragma unroll
        for (int ks = 0; ks < 4; ks++) {       // 4 k16 steps per BK=64
            uint2 alo[4], ahi[4];
            #pragma unroll
            for (int mt = 0; mt < 4; mt++) {
                int r = wm + mt * 16;
                alo[mt] = *(const uint2*)&Ab[(r + g) * 40 + ks * 8 + 2 * tg];
                ahi[mt] = *(const uint2*)&Ab[(r + g + 8) * 40 + ks * 8 + 2 * tg];
            }
            #pragma unroll
            for (int nt = 0; nt < 4; nt++) {
                uint2 bb = *(const uint2*)&Bbuf[(wn + nt * 8 + g) * 40 + ks * 8 + 2 * tg];
                #pragma unroll
                for (int mt = 0; mt < 4; mt++)
                    mma16(acc[mt][nt], alo[mt].x, ahi[mt].x, alo[mt].y, ahi[mt].y,
                          bb.x, bb.y);
            }
        }
        __syncthreads();
    }

    #pragma unroll
    for (int mt = 0; mt < 4; mt++)
        #pragma unroll
        for (int nt = 0; nt < 4; nt++) {
            int r0 = m0 + wm + mt * 16 + g;
            int c  = n0 + wn + nt * 8 + 2 * tg;
            float2 v0 = make_float2(acc[mt][nt][0], acc[mt][nt][1]);
            float2 v1 = make_float2(acc[mt][nt][2], acc[mt][nt][3]);
            *(float2*)&C[(size_t)r0 * N + c] = v0;
            *(float2*)&C[(size_t)(r0 + 8) * N + c] = v1;
        }
}

// ---------------------------------------------------------------------------
// Fused per-head RMSNorm + RoPE; fp32 out (nullable) + fp16 out (nullable,
// with scale applied).
// ---------------------------------------------------------------------------
__global__ __launch_bounds__(128) void norm_rope_kernel(
    const float* __restrict__ raw, int coloff, const float* __restrict__ nw,
    const float* __restrict__ cosT, const float* __restrict__ sinT,
    const int* __restrict__ pos, float* __restrict__ outf,
    __half* __restrict__ outh, float hscale, int NH, int Tout, int toff)
{
    int idx = blockIdx.x;          // (b*T + t)*NH + h
    int h  = idx % NH;
    int bt = idx / NH;
    int t  = bt % Tt;
    int b  = bt / Tt;
    int d  = threadIdx.x;

    __shared__ float zn[128];
    __shared__ float red[4];

    float z = raw[(size_t)bt * 3072 + coloff + h * HD + d];
    float ss = z * z;
    #pragma unroll
    for (int o = 16; o; o >>= 1) ss += __shfl_xor_sync(0xffffffffu, ss, o);
    if ((d & 31) == 0) red[d >> 5] = ss;
    __syncthreads();
    float tot = red[0] + red[1] + red[2] + red[3];
    float r = rsqrtf(tot * (1.0f / 128.0f) + 1e-6f);
    float v = z * r * nw[d];
    zn[d] = v;
    __syncthreads();

    int p = pos[bt];
    float c = cosT[p * HD + d];
    float s = sinT[p * HD + d];
    float rot = (d < 64) ? -zn[d + 64] : zn[d - 64];
    float o = fmaf(v, c, rot * s);
    size_t oi = (((size_t)b * NH + h) * Tout + (toff + t)) * HD + d;
    if (outf) outf[oi] = o;
    if (outh) outh[oi] = __float2half_rn(o * hscale);
}

// V scatter: exact fp32 into v_full output
__global__ __launch_bounds__(256) void scatter_v_kernel(
    const float* __restrict__ qkv, float* __restrict__ vf)
{
    int i = blockIdx.x * blockDim.x + threadIdx.x;
    const int n = Bb * Tt * Gg * HD;
    if (i >= n) return;
    int d = i & 127;
    int g = (i >> 7) & 3;
    int t = (i >> 9) % Tt;
    int b = i / (HD * Gg * Tt);
    int bt = b * Tt + t;
    vf[(((size_t)(b * Gg + g)) * SS + CACHEN + t) * HD + d] =
        qkv[(size_t)bt * 3072 + 2560 + g * HD + d];
}

// Cache copy: exact fp32 + optional fp16
__global__ __launch_bounds__(256) void copy_cache_kernel(
    const float4* __restrict__ src, float4* __restrict__ dst,
    uint2* __restrict__ dsth)
{
    int i = blockIdx.x * blockDim.x + threadIdx.x;
    const int per = CACHEN * HD / 4;
    const int n4  = Bb * Gg * per;
    if (i >= n4) return;
    int bg = i / per, r = i % per;
    size_t oi = (size_t)bg * (SS * HD / 4) + r;
    float4 v = src[i];
    dst[oi] = v;
    if (dsth) dsth[oi] = make_uint2(ph2(v.x, v.y), ph2(v.z, v.w));
}

// ---------------------------------------------------------------------------
// fp16 flash attention. grid=(T/128, H, B), 256 threads, 131072B smem.
// Q pre-scaled fp16; K fp16 [s][d]; V fp16 transposed+key-permuted [d][s'].
// All fragments single LDS.64, shuffle-free PV.
// ---------------------------------------------------------------------------
__global__ __launch_bounds__(256) void attn_h(
    const __half* __restrict__ qh, const __half* __restrict__ kh,
    const __half* __restrict__ vh, const uint8_t* __restrict__ mask,
    __half* __restrict__ ctxh)
{
    extern __shared__ unsigned sm[];
    unsigned* Qs = sm;                    // [128][72] words
    unsigned* Ks = sm + 128 * 72;         // 2 x [64][72]
    unsigned* Vs = sm + 128 * 72 + 2 * 64 * 72;  // 2 x [128][40]
    uint8_t*  Msk = (uint8_t*)(Vs + 2 * 128 * 40); // 2 x [128][64]
    const int KSTG = 64 * 72, VSTG = 128 * 40;

    int qt = blockIdx.x, h = blockIdx.y, b = blockIdx.z;
    int gh = h >> 2;
    int tid = threadIdx.x, lane = tid & 31, wq = tid >> 5;
    int g = lane >> 2, tg = lane & 3;

    const __half* kb = kh + ((size_t)b * Gg + gh) * SS * HD;
    const __half* vb = vh + ((size_t)b * Gg + gh) * (size_t)HD * SS;
    const uint8_t* mb = mask + ((size_t)b * Tt + qt * 128) * SS;

    // Q tile: 128 rows x 128 halves, stride 72 words (in group 0)
    {
        const __half* qbase = qh + (((size_t)b * Hh + h) * Tt + qt * 128) * HD;
        #pragma unroll
        for (int t = 0; t < 8; t++) {
            int c = tid + (t << 8);
            int row = c >> 4, ch = c & 15;
            unsigned dq = (unsigned)__cvta_generic_to_shared(
                &Qs[row * 72 + ch * 4]);
            CPASYNC16(dq, qbase + (size_t)row * HD + ch * 8);
        }
    }

    auto load_stage = [&](int ti, int s) {
        #pragma unroll
        for (int t = 0; t < 4; t++) {
            int c = tid + (t << 8);
            int krow = c >> 4, kch = c & 15;
            unsigned dk = (unsigned)__cvta_generic_to_shared(
                &Ks[s * KSTG + krow * 72 + kch * 4]);
            CPASYNC16(dk, kb + (size_t)(ti * 64 + krow) * HD + kch * 8);
            int vrow = c >> 3, vch = c & 7;
            unsigned dv = (unsigned)__cvta_generic_to_shared(
                &Vs[s * VSTG + vrow * 40 + vch * 4]);
            CPASYNC16(dv, vb + (size_t)vrow * SS + ti * 64 + vch * 8);
        }
        #pragma unroll
        for (int t = 0; t < 2; t++) {
            int c = tid + (t << 8);
            int row = c >> 2, c16 = (c & 3) << 4;
            unsigned dm = (unsigned)__cvta_generic_to_shared(
                &Msk[s * 8192 + row * 64 + c16]);
            CPASYNC16(dm, mb + (size_t)row * SS + ti * 64 + c16);
        }
        asm volatile("cp.async.commit_group;\n");
    };

    float oacc[16][4];
    #pragma unroll
    for (int nt = 0; nt < 16; nt++)
        #pragma unroll
        for (int e = 0; e < 4; e++) oacc[nt][e] = 0.0f;
    float m0r = -1e30f, m1r = -1e30f, l0 = 0.0f, l1 = 0.0f;
    int qrow = wq * 16;

    load_stage(0, 0);   // commits group containing Q + tile0

    const int NT = SS / 64;
    for (int ti = 0; ti < NT; ti++) {
        if (ti + 1 < NT) {
            load_stage(ti + 1, (ti + 1) & 1);
            asm volatile("cp.async.wait_group 1;\n");
        } else {
            asm volatile("cp.async.wait_group 0;\n");
        }
        __syncthreads();

        const unsigned* Kb = Ks + (ti & 1) * KSTG;
        const unsigned* Vb = Vs + (ti & 1) * VSTG;
        const uint8_t*  Mb = Msk + (ti & 1) * 8192;

        // S = Q K^T : 8 k16 steps over HD=128
        float sacc[8][4];
        #pragma unroll
        for (int nt = 0; nt < 8; nt++)
            #pragma unroll
            for (int e = 0; e < 4; e++) sacc[nt][e] = 0.0f;

        #pragma unroll
        for (int ks = 0; ks < 8; ks++) {
            uint2 qlo = *(const uint2*)&Qs[(qrow + g) * 72 + ks * 8 + 2 * tg];
            uint2 qhi = *(const uint2*)&Qs[(qrow + g + 8) * 72 + ks * 8 + 2 * tg];
            #pragma unroll
            for (int nt = 0; nt < 8; nt++) {
                uint2 kk = *(const uint2*)&Kb[(nt * 8 + g) * 72 + ks * 8 + 2 * tg];
                mma16(sacc[nt], qlo.x, qhi.x, qlo.y, qhi.y, kk.x, kk.y);
            }
        }

        // mask (True = masked out)
        #pragma unroll
        for (int nt = 0; nt < 8; nt++) {
            unsigned short mm0 = *(const unsigned short*)&Mb[(qrow + g) * 64 + nt * 8 + 2 * tg];
            unsigned short mm1 = *(const unsigned short*)&Mb[(qrow + g + 8) * 64 + nt * 8 + 2 * tg];
            if (mm0 & 0x00FF) sacc[nt][0] = -1e30f;
            if (mm0 & 0xFF00) sacc[nt][1] = -1e30f;
            if (mm1 & 0x00FF) sacc[nt][2] = -1e30f;
            if (mm1 & 0xFF00) sacc[nt][3] = -1e30f;
        }

        // online softmax (rows in lane quads)
        float mx0 = -1e30f, mx1 = -1e30f;
        #pragma unroll
        for (int nt = 0; nt < 8; nt++) {
            mx0 = fmaxf(mx0, fmaxf(sacc[nt][0], sacc[nt][1]));
            mx1 = fmaxf(mx1, fmaxf(sacc[nt][2], sacc[nt][3]));
        }
        mx0 = fmaxf(mx0, __shfl_xor_sync(0xffffffffu, mx0, 1));
        mx0 = fmaxf(mx0, __shfl_xor_sync(0xffffffffu, mx0, 2));
        mx1 = fmaxf(mx1, __shfl_xor_sync(0xffffffffu, mx1, 1));
        mx1 = fmaxf(mx1, __shfl_xor_sync(0xffffffffu, mx1, 2));
        float mn0 = fmaxf(m0r, mx0), mn1 = fmaxf(m1r, mx1);
        float al0 = __expf(m0r - mn0), al1 = __expf(m1r - mn1);
        m0r = mn0; m1r = mn1;

        float p[8][4];
        float rs0 = 0.0f, rs1 = 0.0f;
        #pragma unroll
        for (int nt = 0; nt < 8; nt++) {
            p[nt][0] = __expf(sacc[nt][0] - mn0);
            p[nt][1] = __expf(sacc[nt][1] - mn0);
            p[nt][2] = __expf(sacc[nt][2] - mn1);
            p[nt][3] = __expf(sacc[nt][3] - mn1);
            rs0 += p[nt][0] + p[nt][1]; rs1 += p[nt][2] + p[nt][3];
        }
        rs0 += __shfl_xor_sync(0xffffffffu, rs0, 1);
        rs0 += __shfl_xor_sync(0xffffffffu, rs0, 2);
        rs1 += __shfl_xor_sync(0xffffffffu, rs1, 1);
        rs1 += __shfl_xor_sync(0xffffffffu, rs1, 2);
        l0 = l0 * al0 + rs0;
        l1 = l1 * al1 + rs1;

        #pragma unroll
        for (int nt = 0; nt < 16; nt++) {
            oacc[nt][0] *= al0; oacc[nt][1] *= al0;
            oacc[nt][2] *= al1; oacc[nt][3] *= al1;
        }

        // PV: 4 k16 steps over 64 keys; P fragments packed in place
        // (C-layout slots == A-layout slots), V key-permuted => uint2 frags.
        #pragma unroll
        for (int w = 0; w < 4; w++) {
            unsigned a0 = ph2(p[2*w][0],     p[2*w][1]);
            unsigned a1 = ph2(p[2*w][2],     p[2*w][3]);
            unsigned a2 = ph2(p[2*w+1][0],   p[2*w+1][1]);
            unsigned a3 = ph2(p[2*w+1][2],   p[2*w+1][3]);
            #pragma unroll
            for (int nt = 0; nt < 16; nt++) {
                uint2 vv = *(const uint2*)&Vb[(nt * 8 + g) * 40 + w * 8 + 2 * tg];
                mma16(oacc[nt], a0, a1, a2, a3, vv.x, vv.y);
            }
        }
        __syncthreads();
    }

    // epilogue: ctx as fp16 (half2 stores)
    float il0 = 1.0f / l0, il1 = 1.0f / l1;
    int tok0 = qt * 128 + qrow + g;
    #pragma unroll
    for (int nt = 0; nt < 16; nt++) {
        int d = nt * 8 + 2 * tg;
        unsigned w0 = ph2(oacc[nt][0] * il0, oacc[nt][1] * il0);
        unsigned w1 = ph2(oacc[nt][2] * il1, oacc[nt][3] * il1);
        *(unsigned*)&ctxh[(((size_t)b * Tt + tok0) * Hh + h) * HD + d] = w0;
        *(unsigned*)&ctxh[(((size_t)b * Tt + tok0 + 8) * Hh + h) * HD + d] = w1;
    }
}

// ---------------------------------------------------------------------------
extern "C" void kernel_launch(void* const* d_in, const int* in_sizes, int n_in,
                              void* d_out, int out_size)
{
    const float*   x       = (const float*)d_in[0];
    const uint8_t* mask    = (const uint8_t*)d_in[1];
    const float*   cosT    = (const float*)d_in[2];
    const float*   sinT    = (const float*)d_in[3];
    const int*     pos     = (const int*)d_in[4];
    const float*   cache_k = (const float*)d_in[5];
    const float*   cache_v = (const float*)d_in[6];
    const float*   q_w     = (const float*)d_in[7];
    const float*   k_w     = (const float*)d_in[8];
    const float*   v_w     = (const float*)d_in[9];
    const float*   o_w     = (const float*)d_in[10];
    const float*   qn_w    = (const float*)d_in[11];
    const float*   kn_w    = (const float*)d_in[12];

    float* out_ctx = (float*)d_out;
    float* out_k   = out_ctx + (size_t)Bb * Tt * Hh * HD;
    float* out_v   = out_k   + (size_t)Bb * Gg * SS * HD;

    __half *xh, *wqkvh, *owh, *qhp, *ctxh, *khp, *vhp;
    float *qkv;
    cudaGetSymbolAddress((void**)&xh,    g_xh);
    cudaGetSymbolAddress((void**)&wqkvh, g_wqkvh);
    cudaGetSymbolAddress((void**)&owh,   g_owh);
    cudaGetSymbolAddress((void**)&qkv,   g_qkv);
    cudaGetSymbolAddress((void**)&qhp,   g_qh);
    cudaGetSymbolAddress((void**)&ctxh,  g_ctxh);
    cudaGetSymbolAddress((void**)&khp,   g_kh);
    cudaGetSymbolAddress((void**)&vhp,   g_vh);

    // Fork side stream for independent copy/convert work.
    cudaEventRecord(g_res.e0, 0);
    cudaStreamWaitEvent(g_res.s2, g_res.e0, 0);
    {
        int n4 = Bb * Gg * CACHEN * HD / 4;
        int blocks = (n4 + 255) / 256;
        copy_cache_kernel<<<blocks, 256, 0, g_res.s2>>>(
            (const float4*)cache_k, (float4*)out_k, (uint2*)khp);
        copy_cache_kernel<<<blocks, 256, 0, g_res.s2>>>(
            (const float4*)cache_v, (float4*)out_v, nullptr);
        transpose_ow_kernel<<<dim3(64, 64), 256, 0, g_res.s2>>>(o_w, owh);
    }
    cudaEventRecord(g_res.e2, g_res.s2);

    // Main stream: projection chain.
    {
        int n4x = 2048 * 2048 / 4;
        conv_x_kernel<<<(n4x + 255) / 256, 256>>>((const float4*)x, (uint2*)xh, n4x);
        pack_wqkvT_kernel<<<dim3(64, 96), 256>>>(q_w, k_w, v_w, wqkvh);
    }

    // fused QKV projection: [2048,2048] @ [3072,2048]^T, fp16 mma
    size_t gsmem = (size_t)(4 * 128 * 40) * 4;   // 81920 B
    cudaFuncSetAttribute(gemm_h, cudaFuncAttributeMaxDynamicSharedMemorySize, (int)gsmem);
    gemm_h<<<dim3(24, 16), 256, gsmem>>>(xh, wqkvh, qkv, 2048, 3072, 2048);

    // fp16 transposed+permuted V scratch straight from sources
    transpose_v_kernel<<<dim3(SS / 32, HD / 32, Bb * Gg), 256>>>(cache_v, qkv, vhp);

    // RMSNorm + RoPE; Q -> fp16 scratch (pre-scaled); K -> fp32 out + fp16 scratch
    const float scale = 0.08838834764831845f;   // 1/sqrt(128)
    norm_rope_kernel<<<Bb * Tt * Hh, 128>>>(qkv, 0,    qn_w, cosT, sinT, pos,
                                            nullptr, qhp, scale, Hh, Tt, 0);
    norm_rope_kernel<<<Bb * Tt * Gg, 128>>>(qkv, 2048, kn_w, cosT, sinT, pos,
                                            out_k, khp, 1.0f, Gg, SS, CACHEN);

    // V into v_full (exact fp32)
    {
        int n = Bb * Tt * Gg * HD;
        scatter_v_kernel<<<(n + 255) / 256, 256>>>(qkv, out_v);
    }

    // Join: attention needs khp's cache half; O-GEMM needs owh.
    cudaStreamWaitEvent(0, g_res.e2, 0);

    // attention (fp16 mma, cp.async double-buffered, shuffle-free PV)
    size_t smem = (size_t)(128 * 72 + 2 * 64 * 72 + 2 * 128 * 40) * 4 + 2 * 128 * 64;
    cudaFuncSetAttribute(attn_h, cudaFuncAttributeMaxDynamicSharedMemorySize, (int)smem);
    attn_h<<<dim3(Tt / 128, Hh, Bb), 256, smem>>>(qhp, khp, vhp, mask, ctxh);

    // output projection: [2048,2048] @ [2048,2048]^T, fp16 mma
    gemm_h<<<dim3(16, 16), 256, gsmem>>>(ctxh, owh, out_ctx, 2048, 2048, 2048);
}

// round 10
// speedup vs baseline: 11.6386x; 1.0317x over previous
#include <cuda_runtime.h>
#include <cuda_fp16.h>
#include <stdint.h>

#define Bb 4
#define Tt 512
#define Hh 16
#define Gg 4
#define HD 128
#define CACHEN 3584
#define SS 4096

// Scratch (static device arrays; no allocation allowed)
__device__ __half g_xh   [2048*2048];    // fp16 x               [M,K] K-major
__device__ __half g_wqkvh[3072*2048];    // fp16 qkv weights     [N,K] K-major
__device__ __half g_owh  [2048*2048];    // fp16 o_w             [N,K] K-major
__device__ float  g_qkv  [2048*3072];    // fused projection output (fp32)
__device__ __half g_qh   [Bb*Hh*Tt*HD];  // fp16 Q (pre-scaled) [B,H,T,HD]
__device__ __half g_ctxh [Bb*Tt*Hh*HD];  // fp16 ctx [B,T,H*HD]
__device__ __half g_kh   [Bb*Gg*SS*HD];  // fp16 k_full [B,G,S,HD]
__device__ __half g_vh   [Bb*Gg*HD*SS];  // fp16 v_full transposed [B,G,HD,S], keys permuted in 16-groups
__device__ unsigned long long g_mb[Bb*Tt*64]; // mask bitmask: [b*T + t][tile] (bit j = key tile*64+j masked)

// Side-stream resources, created once at program load (before any capture).
struct GpuRes {
    cudaStream_t s2;
    cudaEvent_t e0, e2;
    GpuRes() {
        cudaStreamCreateWithFlags(&s2, cudaStreamNonBlocking);
        cudaEventCreateWithFlags(&e0, cudaEventDisableTiming);
        cudaEventCreateWithFlags(&e2, cudaEventDisableTiming);
    }
};
static GpuRes g_res;

// pack two floats into half2 (lo, hi)
__device__ __forceinline__ unsigned ph2(float lo, float hi) {
    unsigned r;
    asm("cvt.rn.f16x2.f32 %0, %1, %2;" : "=r"(r) : "f"(hi), "f"(lo));
    return r;
}

__device__ __forceinline__ void mma16(float* c,
    unsigned a0, unsigned a1, unsigned a2, unsigned a3,
    unsigned b0, unsigned b1)
{
    asm volatile(
        "mma.sync.aligned.m16n8k16.row.col.f32.f16.f16.f32 "
        "{%0,%1,%2,%3}, {%4,%5,%6,%7}, {%8,%9}, {%0,%1,%2,%3};"
        : "+f"(c[0]), "+f"(c[1]), "+f"(c[2]), "+f"(c[3])
        : "r"(a0), "r"(a1), "r"(a2), "r"(a3), "r"(b0), "r"(b1));
}

#define CPASYNC16(dst_sm, src_gm) \
    asm volatile("cp.async.cg.shared.global [%0], [%1], 16;\n" \
                 :: "r"(dst_sm), "l"(src_gm))

// key permutation within a 16-group so PV B-fragments are contiguous uint2
__device__ __forceinline__ int perm16(int s) {
    return ((s >> 1) & 3) * 4 + ((s >> 3) & 1) * 2 + (s & 1);
}

// ---------------------------------------------------------------------------
// Prep kernels
// ---------------------------------------------------------------------------
__global__ __launch_bounds__(256) void conv_x_kernel(
    const float4* __restrict__ src, uint2* __restrict__ dst, int n4)
{
    int i = blockIdx.x * blockDim.x + threadIdx.x;
    if (i >= n4) return;
    float4 v = src[i];
    dst[i] = make_uint2(ph2(v.x, v.y), ph2(v.z, v.w));
}

// Pack mask bytes into per-tile u64 bitmasks: out[row][tile], row = b*T+t.
__global__ __launch_bounds__(256) void pack_mask_kernel(
    const uint8_t* __restrict__ mask, unsigned long long* __restrict__ out)
{
    int i = blockIdx.x * blockDim.x + threadIdx.x;   // over Bb*Tt*64
    if (i >= Bb * Tt * 64) return;
    int tile = i & 63, row = i >> 6;
    const unsigned long long* src = (const unsigned long long*)
        (mask + (size_t)row * SS + tile * 64);
    unsigned long long bits = 0;
    #pragma unroll
    for (int c = 0; c < 8; c++) {
        unsigned long long w = src[c];
        #pragma unroll
        for (int j = 0; j < 8; j++)
            if ((w >> (8 * j)) & 0xFFull)
                bits |= 1ull << (c * 8 + j);
    }
    out[i] = bits;
}

// Transposed qkv weight pack: dst[n][k] = fp16(w[k][n]) for n in [0,3072)
__global__ __launch_bounds__(256) void pack_wqkvT_kernel(
    const float* __restrict__ qw, const float* __restrict__ kw,
    const float* __restrict__ vw, __half* __restrict__ dst)
{
    __shared__ float tile[32][33];
    int k0 = blockIdx.x << 5;
    int n0 = blockIdx.y << 5;
    int tx = threadIdx.x & 31, ty = threadIdx.x >> 5;
    const float* src; int ncol, nbase;
    if (n0 < 2048)      { src = qw; ncol = 2048; nbase = 0; }
    else if (n0 < 2560) { src = kw; ncol = 512;  nbase = 2048; }
    else                { src = vw; ncol = 512;  nbase = 2560; }
    #pragma unroll
    for (int r = 0; r < 32; r += 8)
        tile[ty + r][tx] = src[(size_t)(k0 + ty + r) * ncol + (n0 - nbase) + tx];
    __syncthreads();
    #pragma unroll
    for (int r = 0; r < 32; r += 8)
        dst[(size_t)(n0 + ty + r) * 2048 + k0 + tx] =
            __float2half_rn(tile[tx][ty + r]);
}

// o_w transpose: dst[n][k] = fp16(src[k][n]), 2048x2048
__global__ __launch_bounds__(256) void transpose_ow_kernel(
    const float* __restrict__ src, __half* __restrict__ dst)
{
    __shared__ float tile[32][33];
    int k0 = blockIdx.x << 5, n0 = blockIdx.y << 5;
    int tx = threadIdx.x & 31, ty = threadIdx.x >> 5;
    #pragma unroll
    for (int r = 0; r < 32; r += 8)
        tile[ty + r][tx] = src[(size_t)(k0 + ty + r) * 2048 + n0 + tx];
    __syncthreads();
    #pragma unroll
    for (int r = 0; r < 32; r += 8)
        dst[(size_t)(n0 + ty + r) * 2048 + k0 + tx] =
            __float2half_rn(tile[tx][ty + r]);
}

// V: transpose + fp16 + key permutation into [bg][d][s'], sources direct.
__global__ __launch_bounds__(256) void transpose_v_kernel(
    const float* __restrict__ cache_v, const float* __restrict__ qkv,
    __half* __restrict__ dst)
{
    __shared__ float tile[32][33];
    int bg = blockIdx.z;
    int b = bg >> 2, g = bg & 3;
    int s0 = blockIdx.x << 5, d0 = blockIdx.y << 5;
    int tx = threadIdx.x & 31, ty = threadIdx.x >> 5;

    if (s0 < CACHEN) {
        const float* s = cache_v + (size_t)bg * CACHEN * HD;
        #pragma unroll
        for (int r = 0; r < 32; r += 8)
            tile[ty + r][tx] = s[(size_t)(s0 + ty + r) * HD + d0 + tx];
    } else {
        #pragma unroll
        for (int r = 0; r < 32; r += 8) {
            int t = s0 + ty + r - CACHEN;
            tile[ty + r][tx] =
                qkv[(size_t)(b * Tt + t) * 3072 + 2560 + g * HD + d0 + tx];
        }
    }
    __syncthreads();
    __half* d = dst + (size_t)bg * HD * SS;
    int sp = s0 + (tx & ~15) + perm16(tx & 15);
    #pragma unroll
    for (int r = 0; r < 32; r += 8)
        d[(size_t)(d0 + ty + r) * SS + sp] = __float2half_rn(tile[tx][ty + r]);
}

// ---------------------------------------------------------------------------
// fp16 GEMM (unchanged from round 9).
// ---------------------------------------------------------------------------
__global__ __launch_bounds__(256, 2) void gemm_h(
    const __half* __restrict__ A, const __half* __restrict__ Bm,
    float* __restrict__ C, int M, int N, int K)
{
    extern __shared__ unsigned sm[];
    unsigned* As = sm;
    unsigned* Bs = sm + 2 * 128 * 40;
    const int STG = 128 * 40;

    int tid = threadIdx.x, lane = tid & 31, warp = tid >> 5;
    int g = lane >> 2, tg = lane & 3;
    int m0 = blockIdx.y << 7, n0 = blockIdx.x << 7;
    int wm = (warp >> 2) << 6, wn = (warp & 3) << 5;

    float acc[4][4][4];
    #pragma unroll
    for (int i = 0; i < 4; i++)
        #pragma unroll
        for (int j = 0; j < 4; j++)
            #pragma unroll
            for (int e = 0; e < 4; e++) acc[i][j][e] = 0.0f;

    auto load_stage = [&](int it) {
        int s = it & 1;
        int k0 = it << 6;
        #pragma unroll
        for (int t = 0; t < 4; t++) {
            int c = tid + (t << 8);
            int row = c >> 3, ch = c & 7;
            unsigned da = (unsigned)__cvta_generic_to_shared(
                &As[s * STG + row * 40 + ch * 4]);
            CPASYNC16(da, A + (size_t)(m0 + row) * K + k0 + ch * 8);
            unsigned db = (unsigned)__cvta_generic_to_shared(
                &Bs[s * STG + row * 40 + ch * 4]);
            CPASYNC16(db, Bm + (size_t)(n0 + row) * K + k0 + ch * 8);
        }
        asm volatile("cp.async.commit_group;\n");
    };

    int niter = K >> 6;
    load_stage(0);

    for (int it = 0; it < niter; it++) {
        if (it + 1 < niter) {
            load_stage(it + 1);
            asm volatile("cp.async.wait_group 1;\n");
        } else {
            asm volatile("cp.async.wait_group 0;\n");
        }
        __syncthreads();

        const unsigned* Ab = As + (it & 1) * STG;
        const unsigned* Bbuf = Bs + (it & 1) * STG;
        #pragma unroll
        for (int ks = 0; ks < 4; ks++) {
            uint2 alo[4], ahi[4];
            #pragma unroll
            for (int mt = 0; mt < 4; mt++) {
                int r = wm + mt * 16;
                alo[mt] = *(const uint2*)&Ab[(r + g) * 40 + ks * 8 + 2 * tg];
                ahi[mt] = *(const uint2*)&Ab[(r + g + 8) * 40 + ks * 8 + 2 * tg];
            }
            #pragma unroll
            for (int nt = 0; nt < 4; nt++) {
                uint2 bb = *(const uint2*)&Bbuf[(wn + nt * 8 + g) * 40 + ks * 8 + 2 * tg];
                #pragma unroll
                for (int mt = 0; mt < 4; mt++)
                    mma16(acc[mt][nt], alo[mt].x, ahi[mt].x, alo[mt].y, ahi[mt].y,
                          bb.x, bb.y);
            }
        }
        __syncthreads();
    }

    #pragma unroll
    for (int mt = 0; mt < 4; mt++)
        #pragma unroll
        for (int nt = 0; nt < 4; nt++) {
            int r0 = m0 + wm + mt * 16 + g;
            int c  = n0 + wn + nt * 8 + 2 * tg;
            float2 v0 = make_float2(acc[mt][nt][0], acc[mt][nt][1]);
            float2 v1 = make_float2(acc[mt][nt][2], acc[mt][nt][3]);
            *(float2*)&C[(size_t)r0 * N + c] = v0;
            *(float2*)&C[(size_t)(r0 + 8) * N + c] = v1;
        }
}

// ---------------------------------------------------------------------------
// Fused per-head RMSNorm + RoPE; fp32 out (nullable) + fp16 out (nullable).
// ---------------------------------------------------------------------------
__global__ __launch_bounds__(128) void norm_rope_kernel(
    const float* __restrict__ raw, int coloff, const float* __restrict__ nw,
    const float* __restrict__ cosT, const float* __restrict__ sinT,
    const int* __restrict__ pos, float* __restrict__ outf,
    __half* __restrict__ outh, float hscale, int NH, int Tout, int toff)
{
    int idx = blockIdx.x;
    int h  = idx % NH;
    int bt = idx / NH;
    int t  = bt % Tt;
    int b  = bt / Tt;
    int d  = threadIdx.x;

    __shared__ float zn[128];
    __shared__ float red[4];

    float z = raw[(size_t)bt * 3072 + coloff + h * HD + d];
    float ss = z * z;
    #pragma unroll
    for (int o = 16; o; o >>= 1) ss += __shfl_xor_sync(0xffffffffu, ss, o);
    if ((d & 31) == 0) red[d >> 5] = ss;
    __syncthreads();
    float tot = red[0] + red[1] + red[2] + red[3];
    float r = rsqrtf(tot * (1.0f / 128.0f) + 1e-6f);
    float v = z * r * nw[d];
    zn[d] = v;
    __syncthreads();

    int p = pos[bt];
    float c = cosT[p * HD + d];
    float s = sinT[p * HD + d];
    float rot = (d < 64) ? -zn[d + 64] : zn[d - 64];
    float o = fmaf(v, c, rot * s);
    size_t oi = (((size_t)b * NH + h) * Tout + (toff + t)) * HD + d;
    if (outf) outf[oi] = o;
    if (outh) outh[oi] = __float2half_rn(o * hscale);
}

// V scatter: exact fp32 into v_full output
__global__ __launch_bounds__(256) void scatter_v_kernel(
    const float* __restrict__ qkv, float* __restrict__ vf)
{
    int i = blockIdx.x * blockDim.x + threadIdx.x;
    const int n = Bb * Tt * Gg * HD;
    if (i >= n) return;
    int d = i & 127;
    int g = (i >> 7) & 3;
    int t = (i >> 9) % Tt;
    int b = i / (HD * Gg * Tt);
    int bt = b * Tt + t;
    vf[(((size_t)(b * Gg + g)) * SS + CACHEN + t) * HD + d] =
        qkv[(size_t)bt * 3072 + 2560 + g * HD + d];
}

// Cache copy: exact fp32 + optional fp16
__global__ __launch_bounds__(256) void copy_cache_kernel(
    const float4* __restrict__ src, float4* __restrict__ dst,
    uint2* __restrict__ dsth)
{
    int i = blockIdx.x * blockDim.x + threadIdx.x;
    const int per = CACHEN * HD / 4;
    const int n4  = Bb * Gg * per;
    if (i >= n4) return;
    int bg = i / per, r = i % per;
    size_t oi = (size_t)bg * (SS * HD / 4) + r;
    float4 v = src[i];
    dst[oi] = v;
    if (dsth) dsth[oi] = make_uint2(ph2(v.x, v.y), ph2(v.z, v.w));
}

// ---------------------------------------------------------------------------
// fp16 flash attention. grid=(T/128, H, B), 256 threads, 114688B smem,
// 2 CTAs/SM (single wave of 256 CTAs). Mask via u64 bitmask LDG (no smem).
// ---------------------------------------------------------------------------
__global__ __launch_bounds__(256, 2) void attn_h(
    const __half* __restrict__ qh, const __half* __restrict__ kh,
    const __half* __restrict__ vh, const unsigned long long* __restrict__ mbits,
    __half* __restrict__ ctxh)
{
    extern __shared__ unsigned sm[];
    unsigned* Qs = sm;                           // [128][72] words
    unsigned* Ks = sm + 128 * 72;                // 2 x [64][72]
    unsigned* Vs = sm + 128 * 72 + 2 * 64 * 72;  // 2 x [128][40]
    const int KSTG = 64 * 72, VSTG = 128 * 40;

    int qt = blockIdx.x, h = blockIdx.y, b = blockIdx.z;
    int gh = h >> 2;
    int tid = threadIdx.x, lane = tid & 31, wq = tid >> 5;
    int g = lane >> 2, tg = lane & 3;

    const __half* kb = kh + ((size_t)b * Gg + gh) * SS * HD;
    const __half* vb = vh + ((size_t)b * Gg + gh) * (size_t)HD * SS;
    const unsigned long long* mb = mbits + ((size_t)b * Tt + qt * 128) * 64;

    // Q tile: 128 rows x 128 halves, stride 72 words
    {
        const __half* qbase = qh + (((size_t)b * Hh + h) * Tt + qt * 128) * HD;
        #pragma unroll
        for (int t = 0; t < 8; t++) {
            int c = tid + (t << 8);
            int row = c >> 4, ch = c & 15;
            unsigned dq = (unsigned)__cvta_generic_to_shared(
                &Qs[row * 72 + ch * 4]);
            CPASYNC16(dq, qbase + (size_t)row * HD + ch * 8);
        }
    }

    auto load_stage = [&](int ti, int s) {
        #pragma unroll
        for (int t = 0; t < 4; t++) {
            int c = tid + (t << 8);
            int krow = c >> 4, kch = c & 15;
            unsigned dk = (unsigned)__cvta_generic_to_shared(
                &Ks[s * KSTG + krow * 72 + kch * 4]);
            CPASYNC16(dk, kb + (size_t)(ti * 64 + krow) * HD + kch * 8);
            int vrow = c >> 3, vch = c & 7;
            unsigned dv = (unsigned)__cvta_generic_to_shared(
                &Vs[s * VSTG + vrow * 40 + vch * 4]);
            CPASYNC16(dv, vb + (size_t)vrow * SS + ti * 64 + vch * 8);
        }
        asm volatile("cp.async.commit_group;\n");
    };

    float oacc[16][4];
    #pragma unroll
    for (int nt = 0; nt < 16; nt++)
        #pragma unroll
        for (int e = 0; e < 4; e++) oacc[nt][e] = 0.0f;
    float m0r = -1e30f, m1r = -1e30f, l0 = 0.0f, l1 = 0.0f;
    int qrow = wq * 16;

    load_stage(0, 0);

    const int NT = SS / 64;
    for (int ti = 0; ti < NT; ti++) {
        // mask bitmasks for this tile (L2/L1-resident, 4-lane broadcast)
        unsigned long long mb0 = mb[(size_t)(qrow + g) * 64 + ti];
        unsigned long long mb1 = mb[(size_t)(qrow + g + 8) * 64 + ti];

        if (ti + 1 < NT) {
            load_stage(ti + 1, (ti + 1) & 1);
            asm volatile("cp.async.wait_group 1;\n");
        } else {
            asm volatile("cp.async.wait_group 0;\n");
        }
        __syncthreads();

        const unsigned* Kb = Ks + (ti & 1) * KSTG;
        const unsigned* Vb = Vs + (ti & 1) * VSTG;

        // S = Q K^T : 8 k16 steps over HD=128
        float sacc[8][4];
        #pragma unroll
        for (int nt = 0; nt < 8; nt++)
            #pragma unroll
            for (int e = 0; e < 4; e++) sacc[nt][e] = 0.0f;

        #pragma unroll
        for (int ks = 0; ks < 8; ks++) {
            uint2 qlo = *(const uint2*)&Qs[(qrow + g) * 72 + ks * 8 + 2 * tg];
            uint2 qhi = *(const uint2*)&Qs[(qrow + g + 8) * 72 + ks * 8 + 2 * tg];
            #pragma unroll
            for (int nt = 0; nt < 8; nt++) {
                uint2 kk = *(const uint2*)&Kb[(nt * 8 + g) * 72 + ks * 8 + 2 * tg];
                mma16(sacc[nt], qlo.x, qhi.x, qlo.y, qhi.y, kk.x, kk.y);
            }
        }

        // mask (bit set = masked out)
        #pragma unroll
        for (int nt = 0; nt < 8; nt++) {
            int sh = nt * 8 + 2 * tg;
            if ((mb0 >> sh) & 1)       sacc[nt][0] = -1e30f;
            if ((mb0 >> (sh + 1)) & 1) sacc[nt][1] = -1e30f;
            if ((mb1 >> sh) & 1)       sacc[nt][2] = -1e30f;
            if ((mb1 >> (sh + 1)) & 1) sacc[nt][3] = -1e30f;
        }

        // online softmax (rows in lane quads)
        float mx0 = -1e30f, mx1 = -1e30f;
        #pragma unroll
        for (int nt = 0; nt < 8; nt++) {
            mx0 = fmaxf(mx0, fmaxf(sacc[nt][0], sacc[nt][1]));
            mx1 = fmaxf(mx1, fmaxf(sacc[nt][2], sacc[nt][3]));
        }
        mx0 = fmaxf(mx0, __shfl_xor_sync(0xffffffffu, mx0, 1));
        mx0 = fmaxf(mx0, __shfl_xor_sync(0xffffffffu, mx0, 2));
        mx1 = fmaxf(mx1, __shfl_xor_sync(0xffffffffu, mx1, 1));
        mx1 = fmaxf(mx1, __shfl_xor_sync(0xffffffffu, mx1, 2));
        float mn0 = fmaxf(m0r, mx0), mn1 = fmaxf(m1r, mx1);
        float al0 = __expf(m0r - mn0), al1 = __expf(m1r - mn1);
        m0r = mn0; m1r = mn1;

        float p[8][4];
        float rs0 = 0.0f, rs1 = 0.0f;
        #pragma unroll
        for (int nt = 0; nt < 8; nt++) {
            p[nt][0] = __expf(sacc[nt][0] - mn0);
            p[nt][1] = __expf(sacc[nt][1] - mn0);
            p[nt][2] = __expf(sacc[nt][2] - mn1);
            p[nt][3] = __expf(sacc[nt][3] - mn1);
            rs0 += p[nt][0] + p[nt][1]; rs1 += p[nt][2] + p[nt][3];
        }
        rs0 += __shfl_xor_sync(0xffffffffu, rs0, 1);
        rs0 += __shfl_xor_sync(0xffffffffu, rs0, 2);
        rs1 += __shfl_xor_sync(0xffffffffu, rs1, 1);
        rs1 += __shfl_xor_sync(0xffffffffu, rs1, 2);
        l0 = l0 * al0 + rs0;
        l1 = l1 * al1 + rs1;

        #pragma unroll
        for (int nt = 0; nt < 16; nt++) {
            oacc[nt][0] *= al0; oacc[nt][1] *= al0;
            oacc[nt][2] *= al1; oacc[nt][3] *= al1;
        }

        // PV: 4 k16 steps over 64 keys (V key-permuted => uint2 frags)
        #pragma unroll
        for (int w = 0; w < 4; w++) {
            unsigned a0 = ph2(p[2*w][0],   p[2*w][1]);
            unsigned a1 = ph2(p[2*w][2],   p[2*w][3]);
            unsigned a2 = ph2(p[2*w+1][0], p[2*w+1][1]);
            unsigned a3 = ph2(p[2*w+1][2], p[2*w+1][3]);
            #pragma unroll
            for (int nt = 0; nt < 16; nt++) {
                uint2 vv = *(const uint2*)&Vb[(nt * 8 + g) * 40 + w * 8 + 2 * tg];
                mma16(oacc[nt], a0, a1, a2, a3, vv.x, vv.y);
            }
        }
        __syncthreads();
    }

    // epilogue: ctx as fp16 (half2 stores)
    float il0 = 1.0f / l0, il1 = 1.0f / l1;
    int tok0 = qt * 128 + qrow + g;
    #pragma unroll
    for (int nt = 0; nt < 16; nt++) {
        int d = nt * 8 + 2 * tg;
        unsigned w0 = ph2(oacc[nt][0] * il0, oacc[nt][1] * il0);
        unsigned w1 = ph2(oacc[nt][2] * il1, oacc[nt][3] * il1);
        *(unsigned*)&ctxh[(((size_t)b * Tt + tok0) * Hh + h) * HD + d] = w0;
        *(unsigned*)&ctxh[(((size_t)b * Tt + tok0 + 8) * Hh + h) * HD + d] = w1;
    }
}

// ---------------------------------------------------------------------------
extern "C" void kernel_launch(void* const* d_in, const int* in_sizes, int n_in,
                              void* d_out, int out_size)
{
    const float*   x       = (const float*)d_in[0];
    const uint8_t* mask    = (const uint8_t*)d_in[1];
    const float*   cosT    = (const float*)d_in[2];
    const float*   sinT    = (const float*)d_in[3];
    const int*     pos     = (const int*)d_in[4];
    const float*   cache_k = (const float*)d_in[5];
    const float*   cache_v = (const float*)d_in[6];
    const float*   q_w     = (const float*)d_in[7];
    const float*   k_w     = (const float*)d_in[8];
    const float*   v_w     = (const float*)d_in[9];
    const float*   o_w     = (const float*)d_in[10];
    const float*   qn_w    = (const float*)d_in[11];
    const float*   kn_w    = (const float*)d_in[12];

    float* out_ctx = (float*)d_out;
    float* out_k   = out_ctx + (size_t)Bb * Tt * Hh * HD;
    float* out_v   = out_k   + (size_t)Bb * Gg * SS * HD;

    __half *xh, *wqkvh, *owh, *qhp, *ctxh, *khp, *vhp;
    float *qkv;
    unsigned long long *mbp;
    cudaGetSymbolAddress((void**)&xh,    g_xh);
    cudaGetSymbolAddress((void**)&wqkvh, g_wqkvh);
    cudaGetSymbolAddress((void**)&owh,   g_owh);
    cudaGetSymbolAddress((void**)&qkv,   g_qkv);
    cudaGetSymbolAddress((void**)&qhp,   g_qh);
    cudaGetSymbolAddress((void**)&ctxh,  g_ctxh);
    cudaGetSymbolAddress((void**)&khp,   g_kh);
    cudaGetSymbolAddress((void**)&vhp,   g_vh);
    cudaGetSymbolAddress((void**)&mbp,   g_mb);

    // Fork side stream for independent copy/convert work.
    cudaEventRecord(g_res.e0, 0);
    cudaStreamWaitEvent(g_res.s2, g_res.e0, 0);
    {
        int n4 = Bb * Gg * CACHEN * HD / 4;
        int blocks = (n4 + 255) / 256;
        copy_cache_kernel<<<blocks, 256, 0, g_res.s2>>>(
            (const float4*)cache_k, (float4*)out_k, (uint2*)khp);
        copy_cache_kernel<<<blocks, 256, 0, g_res.s2>>>(
            (const float4*)cache_v, (float4*)out_v, nullptr);
        transpose_ow_kernel<<<dim3(64, 64), 256, 0, g_res.s2>>>(o_w, owh);
        int nm = Bb * Tt * 64;
        pack_mask_kernel<<<(nm + 255) / 256, 256, 0, g_res.s2>>>(mask, mbp);
    }
    cudaEventRecord(g_res.e2, g_res.s2);

    // Main stream: projection chain.
    {
        int n4x = 2048 * 2048 / 4;
        conv_x_kernel<<<(n4x + 255) / 256, 256>>>((const float4*)x, (uint2*)xh, n4x);
        pack_wqkvT_kernel<<<dim3(64, 96), 256>>>(q_w, k_w, v_w, wqkvh);
    }

    // fused QKV projection: [2048,2048] @ [3072,2048]^T, fp16 mma
    size_t gsmem = (size_t)(4 * 128 * 40) * 4;
    cudaFuncSetAttribute(gemm_h, cudaFuncAttributeMaxDynamicSharedMemorySize, (int)gsmem);
    gemm_h<<<dim3(24, 16), 256, gsmem>>>(xh, wqkvh, qkv, 2048, 3072, 2048);

    // fp16 transposed+permuted V scratch straight from sources
    transpose_v_kernel<<<dim3(SS / 32, HD / 32, Bb * Gg), 256>>>(cache_v, qkv, vhp);

    // RMSNorm + RoPE; Q -> fp16 scratch (pre-scaled); K -> fp32 out + fp16 scratch
    const float scale = 0.08838834764831845f;   // 1/sqrt(128)
    norm_rope_kernel<<<Bb * Tt * Hh, 128>>>(qkv, 0,    qn_w, cosT, sinT, pos,
                                            nullptr, qhp, scale, Hh, Tt, 0);
    norm_rope_kernel<<<Bb * Tt * Gg, 128>>>(qkv, 2048, kn_w, cosT, sinT, pos,
                                            out_k, khp, 1.0f, Gg, SS, CACHEN);

    // V into v_full (exact fp32)
    {
        int n = Bb * Tt * Gg * HD;
        scatter_v_kernel<<<(n + 255) / 256, 256>>>(qkv, out_v);
    }

    // Join: attention needs khp's cache half + mask bits; O-GEMM needs owh.
    cudaStreamWaitEvent(0, g_res.e2, 0);

    // attention (fp16 mma, 2 CTAs/SM, bitmask mask path)
    size_t smem = (size_t)(128 * 72 + 2 * 64 * 72 + 2 * 128 * 40) * 4;  // 114688
    cudaFuncSetAttribute(attn_h, cudaFuncAttributeMaxDynamicSharedMemorySize, (int)smem);
    attn_h<<<dim3(Tt / 128, Hh, Bb), 256, smem>>>(qhp, khp, vhp, mbp, ctxh);

    // output projection: [2048,2048] @ [2048,2048]^T, fp16 mma
    gemm_h<<<dim3(16, 16), 256, gsmem>>>(ctxh, owh, out_ctx, 2048, 2048, 2048);
}